// round 1
// baseline (speedup 1.0000x reference)
#include <cuda_runtime.h>
#include <math.h>

#define BB 2
#define SS 2048
#define HH 1024
#define NHH 16
#define HD 64
#define BS (BB*SS)     /* 4096 rows */
#define H3 (3*HH)      /* 3072 */

// ---------------- scratch (no allocations allowed) ----------------
__device__ float g_xn [BS*HH];   // 16 MiB
__device__ float g_qkv[BS*H3];   // 48 MiB
__device__ float g_ctx[BS*HH];   // 16 MiB

// ---------------- LayerNorm ----------------
__global__ __launch_bounds__(256) void ln_kernel(const float* __restrict__ x,
                                                 const float* __restrict__ w,
                                                 const float* __restrict__ bb,
                                                 float* __restrict__ out)
{
    int row = blockIdx.x;
    int t = threadIdx.x;
    const float* xr = x + (size_t)row*HH;
    float v[4];
    float s = 0.f, sq = 0.f;
#pragma unroll
    for (int i = 0; i < 4; i++) { v[i] = xr[t + 256*i]; s += v[i]; sq += v[i]*v[i]; }
#pragma unroll
    for (int o = 16; o; o >>= 1) {
        s  += __shfl_xor_sync(0xffffffffu, s,  o);
        sq += __shfl_xor_sync(0xffffffffu, sq, o);
    }
    __shared__ float rs[8], rq[8];
    if ((t & 31) == 0) { rs[t>>5] = s; rq[t>>5] = sq; }
    __syncthreads();
    if (t < 32) {
        s  = (t < 8) ? rs[t] : 0.f;
        sq = (t < 8) ? rq[t] : 0.f;
#pragma unroll
        for (int o = 4; o; o >>= 1) {
            s  += __shfl_xor_sync(0xffffffffu, s,  o);
            sq += __shfl_xor_sync(0xffffffffu, sq, o);
        }
        if (t == 0) { rs[0] = s; rq[0] = sq; }
    }
    __syncthreads();
    float mu  = rs[0] * (1.0f/HH);
    float var = rq[0] * (1.0f/HH) - mu*mu;
    float inv = rsqrtf(var + 1e-5f);
    float* orow = out + (size_t)row*HH;
#pragma unroll
    for (int i = 0; i < 4; i++) {
        int c = t + 256*i;
        orow[c] = (v[i] - mu) * inv * w[c] + bb[c];
    }
}

// ---------------- SGEMM 128x128x8, 8x8 per thread ----------------
__global__ __launch_bounds__(256) void sgemm_kernel(const float* __restrict__ A,
                                                    const float* __restrict__ Bm,
                                                    const float* __restrict__ bias,
                                                    float* __restrict__ C,
                                                    int M, int N, int K)
{
    __shared__ float As[8][128];
    __shared__ float Bs[8][128];
    int tid = threadIdx.x;
    int bm = blockIdx.y << 7, bn = blockIdx.x << 7;
    int arow = tid >> 1, acol = (tid & 1) << 2;
    int brow = tid >> 5, bcol = (tid & 31) << 2;
    int tr = (tid >> 4) << 3, tc = (tid & 15) << 3;

    float acc[8][8];
#pragma unroll
    for (int i = 0; i < 8; i++)
#pragma unroll
        for (int j = 0; j < 8; j++) acc[i][j] = 0.f;

    const float* aptr = A + (size_t)(bm + arow)*K + acol;
    const float* bptr = Bm + (size_t)brow*N + bn + bcol;

    for (int k0 = 0; k0 < K; k0 += 8) {
        float4 av = *(const float4*)(aptr + k0);
        float4 bv = *(const float4*)(bptr + (size_t)k0*N);
        As[acol+0][arow] = av.x;
        As[acol+1][arow] = av.y;
        As[acol+2][arow] = av.z;
        As[acol+3][arow] = av.w;
        *(float4*)(&Bs[brow][bcol]) = bv;
        __syncthreads();
#pragma unroll
        for (int kk = 0; kk < 8; kk++) {
            float ar[8], br[8];
            *(float4*)(ar)   = *(const float4*)(&As[kk][tr]);
            *(float4*)(ar+4) = *(const float4*)(&As[kk][tr+4]);
            *(float4*)(br)   = *(const float4*)(&Bs[kk][tc]);
            *(float4*)(br+4) = *(const float4*)(&Bs[kk][tc+4]);
#pragma unroll
            for (int i = 0; i < 8; i++)
#pragma unroll
                for (int j = 0; j < 8; j++)
                    acc[i][j] += ar[i] * br[j];
        }
        __syncthreads();
    }

#pragma unroll
    for (int i = 0; i < 8; i++) {
        float* crow = C + (size_t)(bm + tr + i)*N + bn + tc;
#pragma unroll
        for (int j = 0; j < 8; j++)
            crow[j] = acc[i][j] + bias[bn + tc + j];
    }
}

// ---------------- Rotary (full head, rotary_dim == HD == 64) ----------------
__global__ __launch_bounds__(256) void rotary_kernel(float* __restrict__ qkv)
{
    int idx = blockIdx.x * blockDim.x + threadIdx.x;   // BS*NH*32 threads
    int d   = idx & 31;
    int h   = (idx >> 5) & (NHH - 1);
    int row = idx >> 9;                 // b*S + s
    int pos = row & (SS - 1);

    // inv_freq = 10000^(-d/32) = exp(-d * ln(1e4)/32)
    const float k = 0.28782313662425575f;   // ln(10000)/32
    float invf = expf(-k * (float)d);
    float fr = (float)pos * invf;
    float c = cosf(fr), sn = sinf(fr);

    float* qp = qkv + (size_t)row * H3 + h * HD;
    float* kp = qp + HH;

    float x1 = qp[d], x2 = qp[d + 32];
    qp[d]      = x1 * c - x2 * sn;
    qp[d + 32] = x2 * c + x1 * sn;

    x1 = kp[d]; x2 = kp[d + 32];
    kp[d]      = x1 * c - x2 * sn;
    kp[d + 32] = x2 * c + x1 * sn;
}

// ---------------- Flash attention (online softmax), fp32 ----------------
// grid (S/64, NH, B), 256 threads. 64 query rows/block, 32-key tiles.
// Warp w owns rows w*8..w*8+7; lane owns key `lane` in the tile and
// output dims (lane, lane+32).
__global__ __launch_bounds__(256) void attn_kernel(const float* __restrict__ qkv,
                                                   const int* __restrict__ mask,
                                                   float* __restrict__ ctx)
{
    __shared__ float Qs[64*64];      // pre-scaled Q tile
    __shared__ float Ks[32*65];      // padded for conflict-free row reads
    __shared__ float Vs[32*64];
    __shared__ float Ps[8*32];       // per-warp probability staging
    __shared__ float Bias[32];

    int qb = blockIdx.x, h = blockIdx.y, b = blockIdx.z;
    int tid = threadIdx.x, wid = tid >> 5, lane = tid & 31;

    const float* qbase = qkv + ((size_t)(b*SS) + qb*64) * H3 + h * HD;
    for (int i = tid; i < 64*64; i += 256) {
        int r = i >> 6, d = i & 63;
        Qs[i] = qbase[(size_t)r * H3 + d] * 0.125f;   // 1/sqrt(64)
    }

    float m[8], lsum[8], o0[8], o1[8];
#pragma unroll
    for (int i = 0; i < 8; i++) { m[i] = -1e30f; lsum[i] = 0.f; o0[i] = 0.f; o1[i] = 0.f; }

    int ntiles = 2*qb + 2;   // keys 0 .. qb*64+63, tiles of 32
    for (int kt = 0; kt < ntiles; kt++) {
        __syncthreads();
        const float* kbase = qkv + ((size_t)(b*SS) + kt*32) * H3 + HH + h * HD;
        const float* vbase = kbase + HH;
        for (int i = tid; i < 32*64; i += 256) {
            int r = i >> 6, d = i & 63;
            Ks[r*65 + d] = kbase[(size_t)r * H3 + d];
            Vs[r*64 + d] = vbase[(size_t)r * H3 + d];
        }
        if (tid < 32)
            Bias[tid] = (1.0f - (float)mask[b*SS + kt*32 + tid]) * -10000.0f;
        __syncthreads();

        int kg = kt*32 + lane;
        const float* kp = Ks + lane*65;
#pragma unroll
        for (int i = 0; i < 8; i++) {
            int r  = wid*8 + i;
            int qg = qb*64 + r;
            const float* qrow = Qs + r*64;
            float s = 0.f;
#pragma unroll
            for (int d = 0; d < 64; d += 4) {
                float4 q4 = *(const float4*)(qrow + d);
                s += q4.x*kp[d] + q4.y*kp[d+1] + q4.z*kp[d+2] + q4.w*kp[d+3];
            }
            s += Bias[lane];
            if (kg > qg) s = -10000.0f;   // reference replaces, not adds

            float mx = s;
#pragma unroll
            for (int o = 16; o; o >>= 1)
                mx = fmaxf(mx, __shfl_xor_sync(0xffffffffu, mx, o));
            float newm = fmaxf(m[i], mx);
            float corr = __expf(m[i] - newm);
            float p = __expf(s - newm);
            float ps = p;
#pragma unroll
            for (int o = 16; o; o >>= 1)
                ps += __shfl_xor_sync(0xffffffffu, ps, o);
            lsum[i] = lsum[i]*corr + ps;
            m[i] = newm;

            Ps[wid*32 + lane] = p;
            __syncwarp();
            float a0 = o0[i]*corr, a1 = o1[i]*corr;
            const float* pw = Ps + wid*32;
#pragma unroll
            for (int k2 = 0; k2 < 32; k2 += 4) {
                float4 p4 = *(const float4*)(pw + k2);
                a0 += p4.x*Vs[(k2+0)*64 + lane]      + p4.y*Vs[(k2+1)*64 + lane]
                    + p4.z*Vs[(k2+2)*64 + lane]      + p4.w*Vs[(k2+3)*64 + lane];
                a1 += p4.x*Vs[(k2+0)*64 + lane + 32] + p4.y*Vs[(k2+1)*64 + lane + 32]
                    + p4.z*Vs[(k2+2)*64 + lane + 32] + p4.w*Vs[(k2+3)*64 + lane + 32];
            }
            o0[i] = a0; o1[i] = a1;
            __syncwarp();
        }
    }

    float* cbase = ctx + ((size_t)(b*SS) + qb*64) * HH + h * HD;
#pragma unroll
    for (int i = 0; i < 8; i++) {
        int r = wid*8 + i;
        float inv = 1.0f / lsum[i];
        cbase[(size_t)r*HH + lane]      = o0[i]*inv;
        cbase[(size_t)r*HH + lane + 32] = o1[i]*inv;
    }
}

// ---------------- launch ----------------
extern "C" void kernel_launch(void* const* d_in, const int* in_sizes, int n_in,
                              void* d_out, int out_size)
{
    const float* x     = (const float*)d_in[0];
    const int*   maskp = (const int*)  d_in[1];
    const float* nw    = (const float*)d_in[2];
    const float* nb    = (const float*)d_in[3];
    const float* qkvw  = (const float*)d_in[4];
    const float* qkvb  = (const float*)d_in[5];
    const float* ow    = (const float*)d_in[6];
    const float* ob    = (const float*)d_in[7];
    float* out = (float*)d_out;

    float *xn, *qkvB, *ctx;
    cudaGetSymbolAddress((void**)&xn,   g_xn);
    cudaGetSymbolAddress((void**)&qkvB, g_qkv);
    cudaGetSymbolAddress((void**)&ctx,  g_ctx);

    ln_kernel<<<BS, 256>>>(x, nw, nb, xn);
    sgemm_kernel<<<dim3(H3/128, BS/128), 256>>>(xn, qkvw, qkvb, qkvB, BS, H3, HH);
    rotary_kernel<<<(BS*NHH*32)/256, 256>>>(qkvB);
    attn_kernel<<<dim3(SS/64, NHH, BB), 256>>>(qkvB, maskp, ctx);
    sgemm_kernel<<<dim3(HH/128, BS/128), 256>>>(ctx, ow, ob, out, BS, HH, HH);
}

// round 2
// speedup vs baseline: 1.2195x; 1.2195x over previous
#include <cuda_runtime.h>
#include <math.h>
#include <stdint.h>

#define BB 2
#define SS 2048
#define HH 1024
#define NHH 16
#define HD 64
#define BS (BB*SS)     /* 4096 rows */
#define H3 (3*HH)      /* 3072 */

// ---------------- scratch (no allocations allowed) ----------------
__device__ float g_xn [BS*HH];   // 16 MiB
__device__ float g_qkv[BS*H3];   // 48 MiB
__device__ float g_ctx[BS*HH];   // 16 MiB

// ---------------- LayerNorm ----------------
__global__ __launch_bounds__(256) void ln_kernel(const float* __restrict__ x,
                                                 const float* __restrict__ w,
                                                 const float* __restrict__ bb,
                                                 float* __restrict__ out)
{
    int row = blockIdx.x;
    int t = threadIdx.x;
    const float* xr = x + (size_t)row*HH;
    float v[4];
    float s = 0.f, sq = 0.f;
#pragma unroll
    for (int i = 0; i < 4; i++) { v[i] = xr[t + 256*i]; s += v[i]; sq += v[i]*v[i]; }
#pragma unroll
    for (int o = 16; o; o >>= 1) {
        s  += __shfl_xor_sync(0xffffffffu, s,  o);
        sq += __shfl_xor_sync(0xffffffffu, sq, o);
    }
    __shared__ float rs[8], rq[8];
    if ((t & 31) == 0) { rs[t>>5] = s; rq[t>>5] = sq; }
    __syncthreads();
    if (t < 32) {
        s  = (t < 8) ? rs[t] : 0.f;
        sq = (t < 8) ? rq[t] : 0.f;
#pragma unroll
        for (int o = 4; o; o >>= 1) {
            s  += __shfl_xor_sync(0xffffffffu, s,  o);
            sq += __shfl_xor_sync(0xffffffffu, sq, o);
        }
        if (t == 0) { rs[0] = s; rq[0] = sq; }
    }
    __syncthreads();
    float mu  = rs[0] * (1.0f/HH);
    float var = rq[0] * (1.0f/HH) - mu*mu;
    float inv = rsqrtf(var + 1e-5f);
    float* orow = out + (size_t)row*HH;
#pragma unroll
    for (int i = 0; i < 4; i++) {
        int c = t + 256*i;
        orow[c] = (v[i] - mu) * inv * w[c] + bb[c];
    }
}

// ---------------- TF32 tensor-core GEMM 128x128x16 ----------------
// C[M,N] = A[M,K] @ B[K,N] + bias.  mma.sync.m16n8k8 tf32, 8 warps,
// warp tile 64x32 (4x4 of 16x8). Smem stride 136 words = conflict-free.
__device__ __forceinline__ uint32_t f2tf32(float f) {
    uint32_t u;
    asm("cvt.rna.tf32.f32 %0, %1;" : "=r"(u) : "f"(f));
    return u;
}

__global__ __launch_bounds__(256) void tf32_gemm(const float* __restrict__ A,
                                                 const float* __restrict__ B,
                                                 const float* __restrict__ bias,
                                                 float* __restrict__ C,
                                                 int M, int N, int K)
{
    __shared__ uint32_t As[16][136];   // [k][m]
    __shared__ uint32_t Bs[16][136];   // [k][n]

    int tid  = threadIdx.x;
    int lane = tid & 31, warp = tid >> 5;
    int bm = blockIdx.y << 7, bn = blockIdx.x << 7;
    int warpM = (warp >> 2) << 6;      // 0 / 64
    int warpN = (warp & 3) << 5;       // 0 / 32 / 64 / 96

    // global-load assignments
    int arow = tid & 127;
    int acol = (tid >> 7) << 3;        // 0 or 8
    const float* aptr = A + (size_t)(bm + arow) * K + acol;
    int bkr  = tid >> 5;               // 0..7
    int bcol = lane << 2;
    const float* bptr = B + (size_t)bkr * N + bn + bcol;

    float acc[4][4][4];
#pragma unroll
    for (int mt = 0; mt < 4; mt++)
#pragma unroll
        for (int nt = 0; nt < 4; nt++)
#pragma unroll
            for (int e = 0; e < 4; e++) acc[mt][nt][e] = 0.f;

    float4 aReg[2], bReg[2];
    aReg[0] = *(const float4*)(aptr);
    aReg[1] = *(const float4*)(aptr + 4);
    bReg[0] = *(const float4*)(bptr);
    bReg[1] = *(const float4*)(bptr + (size_t)8 * N);

    // initial smem fill
    {
        float av0[4] = {aReg[0].x, aReg[0].y, aReg[0].z, aReg[0].w};
        float av1[4] = {aReg[1].x, aReg[1].y, aReg[1].z, aReg[1].w};
#pragma unroll
        for (int j = 0; j < 4; j++) {
            As[acol + j][arow]     = f2tf32(av0[j]);
            As[acol + 4 + j][arow] = f2tf32(av1[j]);
        }
        Bs[bkr][bcol+0] = f2tf32(bReg[0].x); Bs[bkr][bcol+1] = f2tf32(bReg[0].y);
        Bs[bkr][bcol+2] = f2tf32(bReg[0].z); Bs[bkr][bcol+3] = f2tf32(bReg[0].w);
        Bs[bkr+8][bcol+0] = f2tf32(bReg[1].x); Bs[bkr+8][bcol+1] = f2tf32(bReg[1].y);
        Bs[bkr+8][bcol+2] = f2tf32(bReg[1].z); Bs[bkr+8][bcol+3] = f2tf32(bReg[1].w);
    }
    __syncthreads();

    for (int k0 = 0; k0 < K; k0 += 16) {
        bool more = (k0 + 16) < K;
        if (more) {
            aReg[0] = *(const float4*)(aptr + k0 + 16);
            aReg[1] = *(const float4*)(aptr + k0 + 20);
            bReg[0] = *(const float4*)(bptr + (size_t)(k0 + 16) * N);
            bReg[1] = *(const float4*)(bptr + (size_t)(k0 + 24) * N);
        }

#pragma unroll
        for (int ks = 0; ks < 2; ks++) {
            uint32_t af[4][4], bf[4][2];
            int kr = ks*8 + (lane & 3);
            int am = warpM + (lane >> 2);
#pragma unroll
            for (int mt = 0; mt < 4; mt++) {
                af[mt][0] = As[kr][am + mt*16];
                af[mt][1] = As[kr][am + mt*16 + 8];
                af[mt][2] = As[kr+4][am + mt*16];
                af[mt][3] = As[kr+4][am + mt*16 + 8];
            }
            int bn0 = warpN + (lane >> 2);
#pragma unroll
            for (int nt = 0; nt < 4; nt++) {
                bf[nt][0] = Bs[kr][bn0 + nt*8];
                bf[nt][1] = Bs[kr+4][bn0 + nt*8];
            }
#pragma unroll
            for (int mt = 0; mt < 4; mt++)
#pragma unroll
                for (int nt = 0; nt < 4; nt++) {
                    asm volatile(
                        "mma.sync.aligned.m16n8k8.row.col.f32.tf32.tf32.f32 "
                        "{%0,%1,%2,%3}, {%4,%5,%6,%7}, {%8,%9}, {%0,%1,%2,%3};"
                        : "+f"(acc[mt][nt][0]), "+f"(acc[mt][nt][1]),
                          "+f"(acc[mt][nt][2]), "+f"(acc[mt][nt][3])
                        : "r"(af[mt][0]), "r"(af[mt][1]), "r"(af[mt][2]), "r"(af[mt][3]),
                          "r"(bf[nt][0]), "r"(bf[nt][1]));
                }
        }
        __syncthreads();

        if (more) {
            float av0[4] = {aReg[0].x, aReg[0].y, aReg[0].z, aReg[0].w};
            float av1[4] = {aReg[1].x, aReg[1].y, aReg[1].z, aReg[1].w};
#pragma unroll
            for (int j = 0; j < 4; j++) {
                As[acol + j][arow]     = f2tf32(av0[j]);
                As[acol + 4 + j][arow] = f2tf32(av1[j]);
            }
            Bs[bkr][bcol+0] = f2tf32(bReg[0].x); Bs[bkr][bcol+1] = f2tf32(bReg[0].y);
            Bs[bkr][bcol+2] = f2tf32(bReg[0].z); Bs[bkr][bcol+3] = f2tf32(bReg[0].w);
            Bs[bkr+8][bcol+0] = f2tf32(bReg[1].x); Bs[bkr+8][bcol+1] = f2tf32(bReg[1].y);
            Bs[bkr+8][bcol+2] = f2tf32(bReg[1].z); Bs[bkr+8][bcol+3] = f2tf32(bReg[1].w);
            __syncthreads();
        }
    }

    // epilogue
#pragma unroll
    for (int mt = 0; mt < 4; mt++) {
        int row0 = bm + warpM + mt*16 + (lane >> 2);
#pragma unroll
        for (int nt = 0; nt < 4; nt++) {
            int col = bn + warpN + nt*8 + ((lane & 3) << 1);
            float b0 = bias[col], b1 = bias[col + 1];
            float2 v0 = make_float2(acc[mt][nt][0] + b0, acc[mt][nt][1] + b1);
            float2 v1 = make_float2(acc[mt][nt][2] + b0, acc[mt][nt][3] + b1);
            *(float2*)(C + (size_t)row0 * N + col)       = v0;
            *(float2*)(C + (size_t)(row0 + 8) * N + col) = v1;
        }
    }
}

// ---------------- Rotary (full head, rotary_dim == HD == 64) ----------------
__global__ __launch_bounds__(256) void rotary_kernel(float* __restrict__ qkv)
{
    int idx = blockIdx.x * blockDim.x + threadIdx.x;   // BS*NH*32 threads
    int d   = idx & 31;
    int h   = (idx >> 5) & (NHH - 1);
    int row = idx >> 9;                 // b*S + s
    int pos = row & (SS - 1);

    const float k = 0.28782313662425575f;   // ln(10000)/32
    float invf = expf(-k * (float)d);
    float fr = (float)pos * invf;
    float c = cosf(fr), sn = sinf(fr);

    float* qp = qkv + (size_t)row * H3 + h * HD;
    float* kp = qp + HH;

    float x1 = qp[d], x2 = qp[d + 32];
    qp[d]      = x1 * c - x2 * sn;
    qp[d + 32] = x2 * c + x1 * sn;

    x1 = kp[d]; x2 = kp[d + 32];
    kp[d]      = x1 * c - x2 * sn;
    kp[d + 32] = x2 * c + x1 * sn;
}

// ---------------- Flash attention (online softmax), fp32 ----------------
__global__ __launch_bounds__(256) void attn_kernel(const float* __restrict__ qkv,
                                                   const int* __restrict__ mask,
                                                   float* __restrict__ ctx)
{
    __shared__ float Qs[64*64];      // pre-scaled Q tile
    __shared__ float Ks[32*65];      // padded for conflict-free row reads
    __shared__ float Vs[32*64];
    __shared__ float Ps[8*32];       // per-warp probability staging
    __shared__ float Bias[32];

    int qb = blockIdx.x, h = blockIdx.y, b = blockIdx.z;
    int tid = threadIdx.x, wid = tid >> 5, lane = tid & 31;

    const float* qbase = qkv + ((size_t)(b*SS) + qb*64) * H3 + h * HD;
    for (int i = tid; i < 64*64; i += 256) {
        int r = i >> 6, d = i & 63;
        Qs[i] = qbase[(size_t)r * H3 + d] * 0.125f;   // 1/sqrt(64)
    }

    float m[8], lsum[8], o0[8], o1[8];
#pragma unroll
    for (int i = 0; i < 8; i++) { m[i] = -1e30f; lsum[i] = 0.f; o0[i] = 0.f; o1[i] = 0.f; }

    int ntiles = 2*qb + 2;
    for (int kt = 0; kt < ntiles; kt++) {
        __syncthreads();
        const float* kbase = qkv + ((size_t)(b*SS) + kt*32) * H3 + HH + h * HD;
        const float* vbase = kbase + HH;
        for (int i = tid; i < 32*64; i += 256) {
            int r = i >> 6, d = i & 63;
            Ks[r*65 + d] = kbase[(size_t)r * H3 + d];
            Vs[r*64 + d] = vbase[(size_t)r * H3 + d];
        }
        if (tid < 32)
            Bias[tid] = (1.0f - (float)mask[b*SS + kt*32 + tid]) * -10000.0f;
        __syncthreads();

        int kg = kt*32 + lane;
        const float* kp = Ks + lane*65;
#pragma unroll
        for (int i = 0; i < 8; i++) {
            int r  = wid*8 + i;
            int qg = qb*64 + r;
            const float* qrow = Qs + r*64;
            float s = 0.f;
#pragma unroll
            for (int d = 0; d < 64; d += 4) {
                float4 q4 = *(const float4*)(qrow + d);
                s += q4.x*kp[d] + q4.y*kp[d+1] + q4.z*kp[d+2] + q4.w*kp[d+3];
            }
            s += Bias[lane];
            if (kg > qg) s = -10000.0f;

            float mx = s;
#pragma unroll
            for (int o = 16; o; o >>= 1)
                mx = fmaxf(mx, __shfl_xor_sync(0xffffffffu, mx, o));
            float newm = fmaxf(m[i], mx);
            float corr = __expf(m[i] - newm);
            float p = __expf(s - newm);
            float ps = p;
#pragma unroll
            for (int o = 16; o; o >>= 1)
                ps += __shfl_xor_sync(0xffffffffu, ps, o);
            lsum[i] = lsum[i]*corr + ps;
            m[i] = newm;

            Ps[wid*32 + lane] = p;
            __syncwarp();
            float a0 = o0[i]*corr, a1 = o1[i]*corr;
            const float* pw = Ps + wid*32;
#pragma unroll
            for (int k2 = 0; k2 < 32; k2 += 4) {
                float4 p4 = *(const float4*)(pw + k2);
                a0 += p4.x*Vs[(k2+0)*64 + lane]      + p4.y*Vs[(k2+1)*64 + lane]
                    + p4.z*Vs[(k2+2)*64 + lane]      + p4.w*Vs[(k2+3)*64 + lane];
                a1 += p4.x*Vs[(k2+0)*64 + lane + 32] + p4.y*Vs[(k2+1)*64 + lane + 32]
                    + p4.z*Vs[(k2+2)*64 + lane + 32] + p4.w*Vs[(k2+3)*64 + lane + 32];
            }
            o0[i] = a0; o1[i] = a1;
            __syncwarp();
        }
    }

    float* cbase = ctx + ((size_t)(b*SS) + qb*64) * HH + h * HD;
#pragma unroll
    for (int i = 0; i < 8; i++) {
        int r = wid*8 + i;
        float inv = 1.0f / lsum[i];
        cbase[(size_t)r*HH + lane]      = o0[i]*inv;
        cbase[(size_t)r*HH + lane + 32] = o1[i]*inv;
    }
}

// ---------------- launch ----------------
extern "C" void kernel_launch(void* const* d_in, const int* in_sizes, int n_in,
                              void* d_out, int out_size)
{
    const float* x     = (const float*)d_in[0];
    const int*   maskp = (const int*)  d_in[1];
    const float* nw    = (const float*)d_in[2];
    const float* nb    = (const float*)d_in[3];
    const float* qkvw  = (const float*)d_in[4];
    const float* qkvb  = (const float*)d_in[5];
    const float* ow    = (const float*)d_in[6];
    const float* ob    = (const float*)d_in[7];
    float* out = (float*)d_out;

    float *xn, *qkvB, *ctx;
    cudaGetSymbolAddress((void**)&xn,   g_xn);
    cudaGetSymbolAddress((void**)&qkvB, g_qkv);
    cudaGetSymbolAddress((void**)&ctx,  g_ctx);

    ln_kernel<<<BS, 256>>>(x, nw, nb, xn);
    tf32_gemm<<<dim3(H3/128, BS/128), 256>>>(xn, qkvw, qkvb, qkvB, BS, H3, HH);
    rotary_kernel<<<(BS*NHH*32)/256, 256>>>(qkvB);
    attn_kernel<<<dim3(SS/64, NHH, BB), 256>>>(qkvB, maskp, ctx);
    tf32_gemm<<<dim3(HH/128, BS/128), 256>>>(ctx, ow, ob, out, BS, HH, HH);
}

// round 3
// speedup vs baseline: 3.3906x; 2.7803x over previous
#include <cuda_runtime.h>
#include <math.h>
#include <stdint.h>

#define BB 2
#define SS 2048
#define HH 1024
#define NHH 16
#define HD 64
#define BS (BB*SS)     /* 4096 rows */
#define H3 (3*HH)      /* 3072 */

// ---------------- scratch (no allocations allowed) ----------------
__device__ float g_xn [BS*HH];   // 16 MiB
__device__ float g_qkv[BS*H3];   // 48 MiB
__device__ float g_ctx[BS*HH];   // 16 MiB

// ---------------- helpers ----------------
__device__ __forceinline__ uint32_t f2tf32(float f) {
    uint32_t u;
    asm("cvt.rna.tf32.f32 %0, %1;" : "=r"(u) : "f"(f));
    return u;
}
__device__ __forceinline__ void tf32_split(float x, uint32_t& hi, uint32_t& lo) {
    uint32_t h_;
    asm("cvt.rna.tf32.f32 %0, %1;" : "=r"(h_) : "f"(x));
    float r = x - __uint_as_float(h_);
    uint32_t l_;
    asm("cvt.rna.tf32.f32 %0, %1;" : "=r"(l_) : "f"(r));
    hi = h_; lo = l_;
}
__device__ __forceinline__ void mma_tf32(float* c, const uint32_t* a, const uint32_t* b) {
    asm volatile("mma.sync.aligned.m16n8k8.row.col.f32.tf32.tf32.f32 "
        "{%0,%1,%2,%3}, {%4,%5,%6,%7}, {%8,%9}, {%0,%1,%2,%3};"
        : "+f"(c[0]), "+f"(c[1]), "+f"(c[2]), "+f"(c[3])
        : "r"(a[0]), "r"(a[1]), "r"(a[2]), "r"(a[3]), "r"(b[0]), "r"(b[1]));
}

// ---------------- LayerNorm ----------------
__global__ __launch_bounds__(256) void ln_kernel(const float* __restrict__ x,
                                                 const float* __restrict__ w,
                                                 const float* __restrict__ bb,
                                                 float* __restrict__ out)
{
    int row = blockIdx.x;
    int t = threadIdx.x;
    const float* xr = x + (size_t)row*HH;
    float v[4];
    float s = 0.f, sq = 0.f;
#pragma unroll
    for (int i = 0; i < 4; i++) { v[i] = xr[t + 256*i]; s += v[i]; sq += v[i]*v[i]; }
#pragma unroll
    for (int o = 16; o; o >>= 1) {
        s  += __shfl_xor_sync(0xffffffffu, s,  o);
        sq += __shfl_xor_sync(0xffffffffu, sq, o);
    }
    __shared__ float rs[8], rq[8];
    if ((t & 31) == 0) { rs[t>>5] = s; rq[t>>5] = sq; }
    __syncthreads();
    if (t < 32) {
        s  = (t < 8) ? rs[t] : 0.f;
        sq = (t < 8) ? rq[t] : 0.f;
#pragma unroll
        for (int o = 4; o; o >>= 1) {
            s  += __shfl_xor_sync(0xffffffffu, s,  o);
            sq += __shfl_xor_sync(0xffffffffu, sq, o);
        }
        if (t == 0) { rs[0] = s; rq[0] = sq; }
    }
    __syncthreads();
    float mu  = rs[0] * (1.0f/HH);
    float var = rq[0] * (1.0f/HH) - mu*mu;
    float inv = rsqrtf(var + 1e-5f);
    float* orow = out + (size_t)row*HH;
#pragma unroll
    for (int i = 0; i < 4; i++) {
        int c = t + 256*i;
        orow[c] = (v[i] - mu) * inv * w[c] + bb[c];
    }
}

// ---------------- TF32 tensor-core GEMM 128x128x16 ----------------
__global__ __launch_bounds__(256) void tf32_gemm(const float* __restrict__ A,
                                                 const float* __restrict__ B,
                                                 const float* __restrict__ bias,
                                                 float* __restrict__ C,
                                                 int M, int N, int K)
{
    __shared__ uint32_t As[16][136];   // [k][m]
    __shared__ uint32_t Bs[16][136];   // [k][n]

    int tid  = threadIdx.x;
    int lane = tid & 31, warp = tid >> 5;
    int bm = blockIdx.y << 7, bn = blockIdx.x << 7;
    int warpM = (warp >> 2) << 6;
    int warpN = (warp & 3) << 5;

    int arow = tid & 127;
    int acol = (tid >> 7) << 3;
    const float* aptr = A + (size_t)(bm + arow) * K + acol;
    int bkr  = tid >> 5;
    int bcol = lane << 2;
    const float* bptr = B + (size_t)bkr * N + bn + bcol;

    float acc[4][4][4];
#pragma unroll
    for (int mt = 0; mt < 4; mt++)
#pragma unroll
        for (int nt = 0; nt < 4; nt++)
#pragma unroll
            for (int e = 0; e < 4; e++) acc[mt][nt][e] = 0.f;

    float4 aReg[2], bReg[2];
    aReg[0] = *(const float4*)(aptr);
    aReg[1] = *(const float4*)(aptr + 4);
    bReg[0] = *(const float4*)(bptr);
    bReg[1] = *(const float4*)(bptr + (size_t)8 * N);

    {
        float av0[4] = {aReg[0].x, aReg[0].y, aReg[0].z, aReg[0].w};
        float av1[4] = {aReg[1].x, aReg[1].y, aReg[1].z, aReg[1].w};
#pragma unroll
        for (int j = 0; j < 4; j++) {
            As[acol + j][arow]     = f2tf32(av0[j]);
            As[acol + 4 + j][arow] = f2tf32(av1[j]);
        }
        Bs[bkr][bcol+0] = f2tf32(bReg[0].x); Bs[bkr][bcol+1] = f2tf32(bReg[0].y);
        Bs[bkr][bcol+2] = f2tf32(bReg[0].z); Bs[bkr][bcol+3] = f2tf32(bReg[0].w);
        Bs[bkr+8][bcol+0] = f2tf32(bReg[1].x); Bs[bkr+8][bcol+1] = f2tf32(bReg[1].y);
        Bs[bkr+8][bcol+2] = f2tf32(bReg[1].z); Bs[bkr+8][bcol+3] = f2tf32(bReg[1].w);
    }
    __syncthreads();

    for (int k0 = 0; k0 < K; k0 += 16) {
        bool more = (k0 + 16) < K;
        if (more) {
            aReg[0] = *(const float4*)(aptr + k0 + 16);
            aReg[1] = *(const float4*)(aptr + k0 + 20);
            bReg[0] = *(const float4*)(bptr + (size_t)(k0 + 16) * N);
            bReg[1] = *(const float4*)(bptr + (size_t)(k0 + 24) * N);
        }

#pragma unroll
        for (int ks = 0; ks < 2; ks++) {
            uint32_t af[4][4], bf[4][2];
            int kr = ks*8 + (lane & 3);
            int am = warpM + (lane >> 2);
#pragma unroll
            for (int mt = 0; mt < 4; mt++) {
                af[mt][0] = As[kr][am + mt*16];
                af[mt][1] = As[kr][am + mt*16 + 8];
                af[mt][2] = As[kr+4][am + mt*16];
                af[mt][3] = As[kr+4][am + mt*16 + 8];
            }
            int bn0 = warpN + (lane >> 2);
#pragma unroll
            for (int nt = 0; nt < 4; nt++) {
                bf[nt][0] = Bs[kr][bn0 + nt*8];
                bf[nt][1] = Bs[kr+4][bn0 + nt*8];
            }
#pragma unroll
            for (int mt = 0; mt < 4; mt++)
#pragma unroll
                for (int nt = 0; nt < 4; nt++)
                    mma_tf32(acc[mt][nt], af[mt], bf[nt]);
        }
        __syncthreads();

        if (more) {
            float av0[4] = {aReg[0].x, aReg[0].y, aReg[0].z, aReg[0].w};
            float av1[4] = {aReg[1].x, aReg[1].y, aReg[1].z, aReg[1].w};
#pragma unroll
            for (int j = 0; j < 4; j++) {
                As[acol + j][arow]     = f2tf32(av0[j]);
                As[acol + 4 + j][arow] = f2tf32(av1[j]);
            }
            Bs[bkr][bcol+0] = f2tf32(bReg[0].x); Bs[bkr][bcol+1] = f2tf32(bReg[0].y);
            Bs[bkr][bcol+2] = f2tf32(bReg[0].z); Bs[bkr][bcol+3] = f2tf32(bReg[0].w);
            Bs[bkr+8][bcol+0] = f2tf32(bReg[1].x); Bs[bkr+8][bcol+1] = f2tf32(bReg[1].y);
            Bs[bkr+8][bcol+2] = f2tf32(bReg[1].z); Bs[bkr+8][bcol+3] = f2tf32(bReg[1].w);
            __syncthreads();
        }
    }

#pragma unroll
    for (int mt = 0; mt < 4; mt++) {
        int row0 = bm + warpM + mt*16 + (lane >> 2);
#pragma unroll
        for (int nt = 0; nt < 4; nt++) {
            int col = bn + warpN + nt*8 + ((lane & 3) << 1);
            float b0 = bias[col], b1 = bias[col + 1];
            float2 v0 = make_float2(acc[mt][nt][0] + b0, acc[mt][nt][1] + b1);
            float2 v1 = make_float2(acc[mt][nt][2] + b0, acc[mt][nt][3] + b1);
            *(float2*)(C + (size_t)row0 * N + col)       = v0;
            *(float2*)(C + (size_t)(row0 + 8) * N + col) = v1;
        }
    }
}

// ---------------- Rotary ----------------
__global__ __launch_bounds__(256) void rotary_kernel(float* __restrict__ qkv)
{
    int idx = blockIdx.x * blockDim.x + threadIdx.x;
    int d   = idx & 31;
    int h   = (idx >> 5) & (NHH - 1);
    int row = idx >> 9;
    int pos = row & (SS - 1);

    const float k = 0.28782313662425575f;   // ln(10000)/32
    float invf = expf(-k * (float)d);
    float fr = (float)pos * invf;
    float c = cosf(fr), sn = sinf(fr);

    float* qp = qkv + (size_t)row * H3 + h * HD;
    float* kp = qp + HH;

    float x1 = qp[d], x2 = qp[d + 32];
    qp[d]      = x1 * c - x2 * sn;
    qp[d + 32] = x2 * c + x1 * sn;

    x1 = kp[d]; x2 = kp[d + 32];
    kp[d]      = x1 * c - x2 * sn;
    kp[d + 32] = x2 * c + x1 * sn;
}

// ---------------- Flash attention, tf32 tensor cores ----------------
// Block: 64 q rows x 1 head. 4 warps, each 16 q rows. Key tile 32.
// QK^T: tf32 hi/lo split (3 MMAs) ~ fp32 accuracy.
// PV: P single tf32, V hi/lo split (2 MMAs).
__global__ __launch_bounds__(128, 3) void attn_tc_kernel(const float* __restrict__ qkv,
                                                         const int* __restrict__ mask,
                                                         float* __restrict__ ctx)
{
    __shared__ __align__(16) float Ks[32][68];   // [key][dim], pad 68: conflict-free B-frag reads
    __shared__ __align__(16) float Vs[32][72];   // pad 72: conflict-free B-frag reads
    __shared__ float Bias[32];

    int qb = blockIdx.x, h = blockIdx.y, b = blockIdx.z;
    int tid = threadIdx.x, w = tid >> 5, lane = tid & 31;
    int gq = lane >> 2, tq = lane & 3;

    // Q fragments (fp32, pre-scaled by 1/sqrt(64)); split to hi/lo per tile
    const float* qbase = qkv + ((size_t)(b*SS) + qb*64 + w*16) * H3 + h*HD;
    float qf[8][4];
#pragma unroll
    for (int j = 0; j < 8; j++) {
        const float* q0 = qbase + (size_t)gq*H3     + j*8 + tq;
        const float* q1 = qbase + (size_t)(gq+8)*H3 + j*8 + tq;
        qf[j][0] = q0[0] * 0.125f;
        qf[j][1] = q1[0] * 0.125f;
        qf[j][2] = q0[4] * 0.125f;
        qf[j][3] = q1[4] * 0.125f;
    }

    float o[8][4];
#pragma unroll
    for (int nt = 0; nt < 8; nt++)
#pragma unroll
        for (int e = 0; e < 4; e++) o[nt][e] = 0.f;
    float m0 = -1e30f, m1 = -1e30f, l0 = 0.f, l1 = 0.f;

    int row0 = qb*64 + w*16 + gq;   // global q row (and row0+8)
    int ntiles = 2*qb + 2;

    for (int kt = 0; kt < ntiles; kt++) {
        __syncthreads();
        const float* kb = qkv + ((size_t)(b*SS) + kt*32) * H3 + HH + h*HD;
        const float* vb = kb + HH;
#pragma unroll
        for (int i = tid; i < 512; i += 128) {
            int r = i >> 4, c = (i & 15) << 2;
            *(float4*)&Ks[r][c] = *(const float4*)(kb + (size_t)r*H3 + c);
            *(float4*)&Vs[r][c] = *(const float4*)(vb + (size_t)r*H3 + c);
        }
        if (tid < 32)
            Bias[tid] = (1.0f - (float)mask[b*SS + kt*32 + tid]) * -10000.0f;
        __syncthreads();

        // ---- S = Q K^T (hi/lo corrected tf32) ----
        float sc[4][4];
#pragma unroll
        for (int nt = 0; nt < 4; nt++)
#pragma unroll
            for (int e = 0; e < 4; e++) sc[nt][e] = 0.f;

#pragma unroll
        for (int j = 0; j < 8; j++) {
            uint32_t ah[4], al[4];
#pragma unroll
            for (int e = 0; e < 4; e++) tf32_split(qf[j][e], ah[e], al[e]);
#pragma unroll
            for (int nt = 0; nt < 4; nt++) {
                float b0 = Ks[nt*8 + gq][j*8 + tq];
                float b1 = Ks[nt*8 + gq][j*8 + 4 + tq];
                uint32_t bh[2], bl[2];
                tf32_split(b0, bh[0], bl[0]);
                tf32_split(b1, bh[1], bl[1]);
                mma_tf32(sc[nt], ah, bh);
                mma_tf32(sc[nt], ah, bl);
                mma_tf32(sc[nt], al, bh);
            }
        }

        // ---- bias + causal mask (replace with exactly -10000) ----
#pragma unroll
        for (int nt = 0; nt < 4; nt++) {
            int k0 = kt*32 + nt*8 + 2*tq;
            float bs0 = Bias[nt*8 + 2*tq], bs1 = Bias[nt*8 + 2*tq + 1];
            sc[nt][0] += bs0; sc[nt][1] += bs1;
            sc[nt][2] += bs0; sc[nt][3] += bs1;
            if (k0     > row0)     sc[nt][0] = -10000.0f;
            if (k0 + 1 > row0)     sc[nt][1] = -10000.0f;
            if (k0     > row0 + 8) sc[nt][2] = -10000.0f;
            if (k0 + 1 > row0 + 8) sc[nt][3] = -10000.0f;
        }

        // ---- online softmax ----
        float tm0 = -1e30f, tm1 = -1e30f;
#pragma unroll
        for (int nt = 0; nt < 4; nt++) {
            tm0 = fmaxf(tm0, fmaxf(sc[nt][0], sc[nt][1]));
            tm1 = fmaxf(tm1, fmaxf(sc[nt][2], sc[nt][3]));
        }
        tm0 = fmaxf(tm0, __shfl_xor_sync(0xffffffffu, tm0, 1));
        tm0 = fmaxf(tm0, __shfl_xor_sync(0xffffffffu, tm0, 2));
        tm1 = fmaxf(tm1, __shfl_xor_sync(0xffffffffu, tm1, 1));
        tm1 = fmaxf(tm1, __shfl_xor_sync(0xffffffffu, tm1, 2));

        float nm0 = fmaxf(m0, tm0), nm1 = fmaxf(m1, tm1);
        float c0 = __expf(m0 - nm0), c1 = __expf(m1 - nm1);
        m0 = nm0; m1 = nm1;

        float s0 = 0.f, s1 = 0.f;
#pragma unroll
        for (int nt = 0; nt < 4; nt++) {
            sc[nt][0] = __expf(sc[nt][0] - nm0); s0 += sc[nt][0];
            sc[nt][1] = __expf(sc[nt][1] - nm0); s0 += sc[nt][1];
            sc[nt][2] = __expf(sc[nt][2] - nm1); s1 += sc[nt][2];
            sc[nt][3] = __expf(sc[nt][3] - nm1); s1 += sc[nt][3];
        }
        s0 += __shfl_xor_sync(0xffffffffu, s0, 1);
        s0 += __shfl_xor_sync(0xffffffffu, s0, 2);
        s1 += __shfl_xor_sync(0xffffffffu, s1, 1);
        s1 += __shfl_xor_sync(0xffffffffu, s1, 2);
        l0 = l0*c0 + s0;
        l1 = l1*c1 + s1;

#pragma unroll
        for (int nt = 0; nt < 8; nt++) {
            o[nt][0] *= c0; o[nt][1] *= c0;
            o[nt][2] *= c1; o[nt][3] *= c1;
        }

        // ---- O += P V  (P: accumulator->A-operand layout fix via quad shuffles) ----
        uint32_t src0 = (lane & ~3u) | ((uint32_t)tq >> 1);
        uint32_t src1 = src0 | 2u;
        bool odd = tq & 1;
#pragma unroll
        for (int c = 0; c < 4; c++) {
            float v00 = __shfl_sync(0xffffffffu, sc[c][0], src0);
            float v01 = __shfl_sync(0xffffffffu, sc[c][1], src0);
            float v10 = __shfl_sync(0xffffffffu, sc[c][2], src0);
            float v11 = __shfl_sync(0xffffffffu, sc[c][3], src0);
            float w00 = __shfl_sync(0xffffffffu, sc[c][0], src1);
            float w01 = __shfl_sync(0xffffffffu, sc[c][1], src1);
            float w10 = __shfl_sync(0xffffffffu, sc[c][2], src1);
            float w11 = __shfl_sync(0xffffffffu, sc[c][3], src1);
            uint32_t a[4];
            a[0] = f2tf32(odd ? v01 : v00);
            a[1] = f2tf32(odd ? v11 : v10);
            a[2] = f2tf32(odd ? w01 : w00);
            a[3] = f2tf32(odd ? w11 : w10);
#pragma unroll
            for (int nt = 0; nt < 8; nt++) {
                float b0 = Vs[c*8 + tq][nt*8 + gq];
                float b1 = Vs[c*8 + 4 + tq][nt*8 + gq];
                uint32_t bh[2], bl[2];
                tf32_split(b0, bh[0], bl[0]);
                tf32_split(b1, bh[1], bl[1]);
                mma_tf32(o[nt], a, bh);
                mma_tf32(o[nt], a, bl);
            }
        }
    }

    // ---- epilogue ----
    float inv0 = 1.0f / l0, inv1 = 1.0f / l1;
    float* cb = ctx + ((size_t)(b*SS) + qb*64 + w*16) * HH + h*HD;
#pragma unroll
    for (int nt = 0; nt < 8; nt++) {
        float2 u0 = make_float2(o[nt][0]*inv0, o[nt][1]*inv0);
        float2 u1 = make_float2(o[nt][2]*inv1, o[nt][3]*inv1);
        *(float2*)(cb + (size_t)gq*HH      + nt*8 + 2*tq) = u0;
        *(float2*)(cb + (size_t)(gq+8)*HH  + nt*8 + 2*tq) = u1;
    }
}

// ---------------- launch ----------------
extern "C" void kernel_launch(void* const* d_in, const int* in_sizes, int n_in,
                              void* d_out, int out_size)
{
    const float* x     = (const float*)d_in[0];
    const int*   maskp = (const int*)  d_in[1];
    const float* nw    = (const float*)d_in[2];
    const float* nb    = (const float*)d_in[3];
    const float* qkvw  = (const float*)d_in[4];
    const float* qkvb  = (const float*)d_in[5];
    const float* ow    = (const float*)d_in[6];
    const float* ob    = (const float*)d_in[7];
    float* out = (float*)d_out;

    float *xn, *qkvB, *ctx;
    cudaGetSymbolAddress((void**)&xn,   g_xn);
    cudaGetSymbolAddress((void**)&qkvB, g_qkv);
    cudaGetSymbolAddress((void**)&ctx,  g_ctx);

    ln_kernel<<<BS, 256>>>(x, nw, nb, xn);
    tf32_gemm<<<dim3(H3/128, BS/128), 256>>>(xn, qkvw, qkvb, qkvB, BS, H3, HH);
    rotary_kernel<<<(BS*NHH*32)/256, 256>>>(qkvB);
    attn_tc_kernel<<<dim3(SS/64, NHH, BB), 128>>>(qkvB, maskp, ctx);
    tf32_gemm<<<dim3(HH/128, BS/128), 256>>>(ctx, ow, ob, out, BS, HH, HH);
}

// round 4
// speedup vs baseline: 4.4443x; 1.3108x over previous
#include <cuda_runtime.h>
#include <math.h>
#include <stdint.h>

#define BB 2
#define SS 2048
#define HH 1024
#define NHH 16
#define HD 64
#define BS (BB*SS)     /* 4096 rows */
#define H3 (3*HH)      /* 3072 */

// ---------------- scratch (no allocations allowed) ----------------
__device__ float g_xn [BS*HH];   // 16 MiB
__device__ float g_qkv[BS*H3];   // 48 MiB
__device__ float g_ctx[BS*HH];   // 16 MiB

// ---------------- helpers ----------------
__device__ __forceinline__ uint32_t f2tf32(float f) {
    uint32_t u;
    asm("cvt.rna.tf32.f32 %0, %1;" : "=r"(u) : "f"(f));
    return u;
}
__device__ __forceinline__ void mma_tf32(float* c, const uint32_t* a, const uint32_t* b) {
    asm volatile("mma.sync.aligned.m16n8k8.row.col.f32.tf32.tf32.f32 "
        "{%0,%1,%2,%3}, {%4,%5,%6,%7}, {%8,%9}, {%0,%1,%2,%3};"
        : "+f"(c[0]), "+f"(c[1]), "+f"(c[2]), "+f"(c[3])
        : "r"(a[0]), "r"(a[1]), "r"(a[2]), "r"(a[3]), "r"(b[0]), "r"(b[1]));
}

// ---------------- LayerNorm ----------------
__global__ __launch_bounds__(256) void ln_kernel(const float* __restrict__ x,
                                                 const float* __restrict__ w,
                                                 const float* __restrict__ bb,
                                                 float* __restrict__ out)
{
    int row = blockIdx.x;
    int t = threadIdx.x;
    const float* xr = x + (size_t)row*HH;
    float v[4];
    float s = 0.f, sq = 0.f;
#pragma unroll
    for (int i = 0; i < 4; i++) { v[i] = xr[t + 256*i]; s += v[i]; sq += v[i]*v[i]; }
#pragma unroll
    for (int o = 16; o; o >>= 1) {
        s  += __shfl_xor_sync(0xffffffffu, s,  o);
        sq += __shfl_xor_sync(0xffffffffu, sq, o);
    }
    __shared__ float rs[8], rq[8];
    if ((t & 31) == 0) { rs[t>>5] = s; rq[t>>5] = sq; }
    __syncthreads();
    if (t < 32) {
        s  = (t < 8) ? rs[t] : 0.f;
        sq = (t < 8) ? rq[t] : 0.f;
#pragma unroll
        for (int o = 4; o; o >>= 1) {
            s  += __shfl_xor_sync(0xffffffffu, s,  o);
            sq += __shfl_xor_sync(0xffffffffu, sq, o);
        }
        if (t == 0) { rs[0] = s; rq[0] = sq; }
    }
    __syncthreads();
    float mu  = rs[0] * (1.0f/HH);
    float var = rq[0] * (1.0f/HH) - mu*mu;
    float inv = rsqrtf(var + 1e-5f);
    float* orow = out + (size_t)row*HH;
#pragma unroll
    for (int i = 0; i < 4; i++) {
        int c = t + 256*i;
        orow[c] = (v[i] - mu) * inv * w[c] + bb[c];
    }
}

// ---------------- TF32 tensor-core GEMM 128x128x16 ----------------
__global__ __launch_bounds__(256) void tf32_gemm(const float* __restrict__ A,
                                                 const float* __restrict__ B,
                                                 const float* __restrict__ bias,
                                                 float* __restrict__ C,
                                                 int M, int N, int K)
{
    __shared__ uint32_t As[16][136];   // [k][m]
    __shared__ uint32_t Bs[16][136];   // [k][n]

    int tid  = threadIdx.x;
    int lane = tid & 31, warp = tid >> 5;
    int bm = blockIdx.y << 7, bn = blockIdx.x << 7;
    int warpM = (warp >> 2) << 6;
    int warpN = (warp & 3) << 5;

    int arow = tid & 127;
    int acol = (tid >> 7) << 3;
    const float* aptr = A + (size_t)(bm + arow) * K + acol;
    int bkr  = tid >> 5;
    int bcol = lane << 2;
    const float* bptr = B + (size_t)bkr * N + bn + bcol;

    float acc[4][4][4];
#pragma unroll
    for (int mt = 0; mt < 4; mt++)
#pragma unroll
        for (int nt = 0; nt < 4; nt++)
#pragma unroll
            for (int e = 0; e < 4; e++) acc[mt][nt][e] = 0.f;

    float4 aReg[2], bReg[2];
    aReg[0] = *(const float4*)(aptr);
    aReg[1] = *(const float4*)(aptr + 4);
    bReg[0] = *(const float4*)(bptr);
    bReg[1] = *(const float4*)(bptr + (size_t)8 * N);

    {
        float av0[4] = {aReg[0].x, aReg[0].y, aReg[0].z, aReg[0].w};
        float av1[4] = {aReg[1].x, aReg[1].y, aReg[1].z, aReg[1].w};
#pragma unroll
        for (int j = 0; j < 4; j++) {
            As[acol + j][arow]     = f2tf32(av0[j]);
            As[acol + 4 + j][arow] = f2tf32(av1[j]);
        }
        Bs[bkr][bcol+0] = f2tf32(bReg[0].x); Bs[bkr][bcol+1] = f2tf32(bReg[0].y);
        Bs[bkr][bcol+2] = f2tf32(bReg[0].z); Bs[bkr][bcol+3] = f2tf32(bReg[0].w);
        Bs[bkr+8][bcol+0] = f2tf32(bReg[1].x); Bs[bkr+8][bcol+1] = f2tf32(bReg[1].y);
        Bs[bkr+8][bcol+2] = f2tf32(bReg[1].z); Bs[bkr+8][bcol+3] = f2tf32(bReg[1].w);
    }
    __syncthreads();

    for (int k0 = 0; k0 < K; k0 += 16) {
        bool more = (k0 + 16) < K;
        if (more) {
            aReg[0] = *(const float4*)(aptr + k0 + 16);
            aReg[1] = *(const float4*)(aptr + k0 + 20);
            bReg[0] = *(const float4*)(bptr + (size_t)(k0 + 16) * N);
            bReg[1] = *(const float4*)(bptr + (size_t)(k0 + 24) * N);
        }

#pragma unroll
        for (int ks = 0; ks < 2; ks++) {
            uint32_t af[4][4], bf[4][2];
            int kr = ks*8 + (lane & 3);
            int am = warpM + (lane >> 2);
#pragma unroll
            for (int mt = 0; mt < 4; mt++) {
                af[mt][0] = As[kr][am + mt*16];
                af[mt][1] = As[kr][am + mt*16 + 8];
                af[mt][2] = As[kr+4][am + mt*16];
                af[mt][3] = As[kr+4][am + mt*16 + 8];
            }
            int bn0 = warpN + (lane >> 2);
#pragma unroll
            for (int nt = 0; nt < 4; nt++) {
                bf[nt][0] = Bs[kr][bn0 + nt*8];
                bf[nt][1] = Bs[kr+4][bn0 + nt*8];
            }
#pragma unroll
            for (int mt = 0; mt < 4; mt++)
#pragma unroll
                for (int nt = 0; nt < 4; nt++)
                    mma_tf32(acc[mt][nt], af[mt], bf[nt]);
        }
        __syncthreads();

        if (more) {
            float av0[4] = {aReg[0].x, aReg[0].y, aReg[0].z, aReg[0].w};
            float av1[4] = {aReg[1].x, aReg[1].y, aReg[1].z, aReg[1].w};
#pragma unroll
            for (int j = 0; j < 4; j++) {
                As[acol + j][arow]     = f2tf32(av0[j]);
                As[acol + 4 + j][arow] = f2tf32(av1[j]);
            }
            Bs[bkr][bcol+0] = f2tf32(bReg[0].x); Bs[bkr][bcol+1] = f2tf32(bReg[0].y);
            Bs[bkr][bcol+2] = f2tf32(bReg[0].z); Bs[bkr][bcol+3] = f2tf32(bReg[0].w);
            Bs[bkr+8][bcol+0] = f2tf32(bReg[1].x); Bs[bkr+8][bcol+1] = f2tf32(bReg[1].y);
            Bs[bkr+8][bcol+2] = f2tf32(bReg[1].z); Bs[bkr+8][bcol+3] = f2tf32(bReg[1].w);
            __syncthreads();
        }
    }

#pragma unroll
    for (int mt = 0; mt < 4; mt++) {
        int row0 = bm + warpM + mt*16 + (lane >> 2);
#pragma unroll
        for (int nt = 0; nt < 4; nt++) {
            int col = bn + warpN + nt*8 + ((lane & 3) << 1);
            float b0 = bias[col], b1 = bias[col + 1];
            float2 v0 = make_float2(acc[mt][nt][0] + b0, acc[mt][nt][1] + b1);
            float2 v1 = make_float2(acc[mt][nt][2] + b0, acc[mt][nt][3] + b1);
            *(float2*)(C + (size_t)row0 * N + col)       = v0;
            *(float2*)(C + (size_t)(row0 + 8) * N + col) = v1;
        }
    }
}

// ---------------- Rotary ----------------
__global__ __launch_bounds__(256) void rotary_kernel(float* __restrict__ qkv)
{
    int idx = blockIdx.x * blockDim.x + threadIdx.x;
    int d   = idx & 31;
    int h   = (idx >> 5) & (NHH - 1);
    int row = idx >> 9;
    int pos = row & (SS - 1);

    const float k = 0.28782313662425575f;   // ln(10000)/32
    float invf = expf(-k * (float)d);
    float fr = (float)pos * invf;
    float c = cosf(fr), sn = sinf(fr);

    float* qp = qkv + (size_t)row * H3 + h * HD;
    float* kp = qp + HH;

    float x1 = qp[d], x2 = qp[d + 32];
    qp[d]      = x1 * c - x2 * sn;
    qp[d + 32] = x2 * c + x1 * sn;

    x1 = kp[d]; x2 = kp[d + 32];
    kp[d]      = x1 * c - x2 * sn;
    kp[d + 32] = x2 * c + x1 * sn;
}

// ---------------- Flash attention, tf32 tensor cores ----------------
// Block: 64 q rows x 1 head. 4 warps, each 16 q rows. Key tile 32.
// K pre-split hi/lo in smem (2-MMA QK, Q single tf32 pre-rounded).
// V pre-converted to tf32 in smem (1-MMA PV).
__global__ __launch_bounds__(128, 3) void attn_tc_kernel(const float* __restrict__ qkv,
                                                         const int* __restrict__ mask,
                                                         float* __restrict__ ctx)
{
    __shared__ __align__(16) uint32_t KsH[32][68];  // tf32 hi, [key][dim]
    __shared__ __align__(16) uint32_t KsL[32][68];  // tf32 lo
    __shared__ __align__(16) uint32_t VsT[32][72];  // tf32,    [key][dim]
    __shared__ float Bias[32];

    int qb = blockIdx.x, h = blockIdx.y, b = blockIdx.z;
    int tid = threadIdx.x, w = tid >> 5, lane = tid & 31;
    int gq = lane >> 2, tq = lane & 3;

    // Q fragments: pre-scaled, pre-rounded to tf32 ONCE (bit pattern reusable)
    const float* qbase = qkv + ((size_t)(b*SS) + qb*64 + w*16) * H3 + h*HD;
    uint32_t qf[8][4];
#pragma unroll
    for (int j = 0; j < 8; j++) {
        const float* q0 = qbase + (size_t)gq*H3     + j*8 + tq;
        const float* q1 = qbase + (size_t)(gq+8)*H3 + j*8 + tq;
        qf[j][0] = f2tf32(q0[0] * 0.125f);
        qf[j][1] = f2tf32(q1[0] * 0.125f);
        qf[j][2] = f2tf32(q0[4] * 0.125f);
        qf[j][3] = f2tf32(q1[4] * 0.125f);
    }

    float o[8][4];
#pragma unroll
    for (int nt = 0; nt < 8; nt++)
#pragma unroll
        for (int e = 0; e < 4; e++) o[nt][e] = 0.f;
    float m0 = -1e30f, m1 = -1e30f, l0 = 0.f, l1 = 0.f;

    int row0 = qb*64 + w*16 + gq;
    int ntiles = 2*qb + 2;

    for (int kt = 0; kt < ntiles; kt++) {
        __syncthreads();
        const float* kb = qkv + ((size_t)(b*SS) + kt*32) * H3 + HH + h*HD;
        const float* vb = kb + HH;
#pragma unroll
        for (int i = tid; i < 512; i += 128) {
            int r = i >> 4, c = (i & 15) << 2;
            float4 kv = *(const float4*)(kb + (size_t)r*H3 + c);
            float4 vv = *(const float4*)(vb + (size_t)r*H3 + c);
            uint4 kh, kl, vt;
            kh.x = f2tf32(kv.x); kl.x = f2tf32(kv.x - __uint_as_float(kh.x));
            kh.y = f2tf32(kv.y); kl.y = f2tf32(kv.y - __uint_as_float(kh.y));
            kh.z = f2tf32(kv.z); kl.z = f2tf32(kv.z - __uint_as_float(kh.z));
            kh.w = f2tf32(kv.w); kl.w = f2tf32(kv.w - __uint_as_float(kh.w));
            vt.x = f2tf32(vv.x); vt.y = f2tf32(vv.y);
            vt.z = f2tf32(vv.z); vt.w = f2tf32(vv.w);
            *(uint4*)&KsH[r][c] = kh;
            *(uint4*)&KsL[r][c] = kl;
            *(uint4*)&VsT[r][c] = vt;
        }
        if (tid < 32)
            Bias[tid] = (1.0f - (float)mask[b*SS + kt*32 + tid]) * -10000.0f;
        __syncthreads();

        // ---- S = Q K^T (Q single tf32, K hi/lo => 2 MMAs) ----
        float sc[4][4];
#pragma unroll
        for (int nt = 0; nt < 4; nt++)
#pragma unroll
            for (int e = 0; e < 4; e++) sc[nt][e] = 0.f;

#pragma unroll
        for (int j = 0; j < 8; j++) {
#pragma unroll
            for (int nt = 0; nt < 4; nt++) {
                uint32_t bh[2], bl[2];
                bh[0] = KsH[nt*8 + gq][j*8 + tq];
                bh[1] = KsH[nt*8 + gq][j*8 + 4 + tq];
                bl[0] = KsL[nt*8 + gq][j*8 + tq];
                bl[1] = KsL[nt*8 + gq][j*8 + 4 + tq];
                mma_tf32(sc[nt], qf[j], bh);
                mma_tf32(sc[nt], qf[j], bl);
            }
        }

        // ---- bias + causal mask ----
#pragma unroll
        for (int nt = 0; nt < 4; nt++) {
            int k0 = kt*32 + nt*8 + 2*tq;
            float bs0 = Bias[nt*8 + 2*tq], bs1 = Bias[nt*8 + 2*tq + 1];
            sc[nt][0] += bs0; sc[nt][1] += bs1;
            sc[nt][2] += bs0; sc[nt][3] += bs1;
            if (k0     > row0)     sc[nt][0] = -10000.0f;
            if (k0 + 1 > row0)     sc[nt][1] = -10000.0f;
            if (k0     > row0 + 8) sc[nt][2] = -10000.0f;
            if (k0 + 1 > row0 + 8) sc[nt][3] = -10000.0f;
        }

        // ---- online softmax ----
        float tm0 = -1e30f, tm1 = -1e30f;
#pragma unroll
        for (int nt = 0; nt < 4; nt++) {
            tm0 = fmaxf(tm0, fmaxf(sc[nt][0], sc[nt][1]));
            tm1 = fmaxf(tm1, fmaxf(sc[nt][2], sc[nt][3]));
        }
        tm0 = fmaxf(tm0, __shfl_xor_sync(0xffffffffu, tm0, 1));
        tm0 = fmaxf(tm0, __shfl_xor_sync(0xffffffffu, tm0, 2));
        tm1 = fmaxf(tm1, __shfl_xor_sync(0xffffffffu, tm1, 1));
        tm1 = fmaxf(tm1, __shfl_xor_sync(0xffffffffu, tm1, 2));

        float nm0 = fmaxf(m0, tm0), nm1 = fmaxf(m1, tm1);
        float c0 = __expf(m0 - nm0), c1 = __expf(m1 - nm1);
        m0 = nm0; m1 = nm1;

        float s0 = 0.f, s1 = 0.f;
#pragma unroll
        for (int nt = 0; nt < 4; nt++) {
            sc[nt][0] = __expf(sc[nt][0] - nm0); s0 += sc[nt][0];
            sc[nt][1] = __expf(sc[nt][1] - nm0); s0 += sc[nt][1];
            sc[nt][2] = __expf(sc[nt][2] - nm1); s1 += sc[nt][2];
            sc[nt][3] = __expf(sc[nt][3] - nm1); s1 += sc[nt][3];
        }
        s0 += __shfl_xor_sync(0xffffffffu, s0, 1);
        s0 += __shfl_xor_sync(0xffffffffu, s0, 2);
        s1 += __shfl_xor_sync(0xffffffffu, s1, 1);
        s1 += __shfl_xor_sync(0xffffffffu, s1, 2);
        l0 = l0*c0 + s0;
        l1 = l1*c1 + s1;

#pragma unroll
        for (int nt = 0; nt < 8; nt++) {
            o[nt][0] *= c0; o[nt][1] *= c0;
            o[nt][2] *= c1; o[nt][3] *= c1;
        }

        // ---- O += P V (P layout fix via quad shuffles; V single tf32) ----
        uint32_t src0 = (lane & ~3u) | ((uint32_t)tq >> 1);
        uint32_t src1 = src0 | 2u;
        bool odd = tq & 1;
#pragma unroll
        for (int c = 0; c < 4; c++) {
            float v00 = __shfl_sync(0xffffffffu, sc[c][0], src0);
            float v01 = __shfl_sync(0xffffffffu, sc[c][1], src0);
            float v10 = __shfl_sync(0xffffffffu, sc[c][2], src0);
            float v11 = __shfl_sync(0xffffffffu, sc[c][3], src0);
            float w00 = __shfl_sync(0xffffffffu, sc[c][0], src1);
            float w01 = __shfl_sync(0xffffffffu, sc[c][1], src1);
            float w10 = __shfl_sync(0xffffffffu, sc[c][2], src1);
            float w11 = __shfl_sync(0xffffffffu, sc[c][3], src1);
            uint32_t a[4];
            a[0] = f2tf32(odd ? v01 : v00);
            a[1] = f2tf32(odd ? v11 : v10);
            a[2] = f2tf32(odd ? w01 : w00);
            a[3] = f2tf32(odd ? w11 : w10);
#pragma unroll
            for (int nt = 0; nt < 8; nt++) {
                uint32_t bv[2];
                bv[0] = VsT[c*8 + tq][nt*8 + gq];
                bv[1] = VsT[c*8 + 4 + tq][nt*8 + gq];
                mma_tf32(o[nt], a, bv);
            }
        }
    }

    // ---- epilogue ----
    float inv0 = 1.0f / l0, inv1 = 1.0f / l1;
    float* cb = ctx + ((size_t)(b*SS) + qb*64 + w*16) * HH + h*HD;
#pragma unroll
    for (int nt = 0; nt < 8; nt++) {
        float2 u0 = make_float2(o[nt][0]*inv0, o[nt][1]*inv0);
        float2 u1 = make_float2(o[nt][2]*inv1, o[nt][3]*inv1);
        *(float2*)(cb + (size_t)gq*HH      + nt*8 + 2*tq) = u0;
        *(float2*)(cb + (size_t)(gq+8)*HH  + nt*8 + 2*tq) = u1;
    }
}

// ---------------- launch ----------------
extern "C" void kernel_launch(void* const* d_in, const int* in_sizes, int n_in,
                              void* d_out, int out_size)
{
    const float* x     = (const float*)d_in[0];
    const int*   maskp = (const int*)  d_in[1];
    const float* nw    = (const float*)d_in[2];
    const float* nb    = (const float*)d_in[3];
    const float* qkvw  = (const float*)d_in[4];
    const float* qkvb  = (const float*)d_in[5];
    const float* ow    = (const float*)d_in[6];
    const float* ob    = (const float*)d_in[7];
    float* out = (float*)d_out;

    float *xn, *qkvB, *ctx;
    cudaGetSymbolAddress((void**)&xn,   g_xn);
    cudaGetSymbolAddress((void**)&qkvB, g_qkv);
    cudaGetSymbolAddress((void**)&ctx,  g_ctx);

    ln_kernel<<<BS, 256>>>(x, nw, nb, xn);
    tf32_gemm<<<dim3(H3/128, BS/128), 256>>>(xn, qkvw, qkvb, qkvB, BS, H3, HH);
    rotary_kernel<<<(BS*NHH*32)/256, 256>>>(qkvB);
    attn_tc_kernel<<<dim3(SS/64, NHH, BB), 128>>>(qkvB, maskp, ctx);
    tf32_gemm<<<dim3(HH/128, BS/128), 256>>>(ctx, ow, ob, out, BS, HH, HH);
}

// round 5
// speedup vs baseline: 4.6453x; 1.0452x over previous
#include <cuda_runtime.h>
#include <math.h>
#include <stdint.h>

#define BB 2
#define SS 2048
#define HH 1024
#define NHH 16
#define HD 64
#define BS (BB*SS)     /* 4096 rows */
#define H3 (3*HH)      /* 3072 */

// ---------------- scratch (no allocations allowed) ----------------
__device__ float g_xn [BS*HH];   // 16 MiB
__device__ float g_qkv[BS*H3];   // 48 MiB
__device__ float g_ctx[BS*HH];   // 16 MiB

// ---------------- helpers ----------------
__device__ __forceinline__ uint32_t f2tf32(float f) {
    uint32_t u;
    asm("cvt.rna.tf32.f32 %0, %1;" : "=r"(u) : "f"(f));
    return u;
}
__device__ __forceinline__ void mma_tf32(float* c, const uint32_t* a, const uint32_t* b) {
    asm volatile("mma.sync.aligned.m16n8k8.row.col.f32.tf32.tf32.f32 "
        "{%0,%1,%2,%3}, {%4,%5,%6,%7}, {%8,%9}, {%0,%1,%2,%3};"
        : "+f"(c[0]), "+f"(c[1]), "+f"(c[2]), "+f"(c[3])
        : "r"(a[0]), "r"(a[1]), "r"(a[2]), "r"(a[3]), "r"(b[0]), "r"(b[1]));
}

// ---------------- LayerNorm ----------------
__global__ __launch_bounds__(256) void ln_kernel(const float* __restrict__ x,
                                                 const float* __restrict__ w,
                                                 const float* __restrict__ bb,
                                                 float* __restrict__ out)
{
    int row = blockIdx.x;
    int t = threadIdx.x;
    const float* xr = x + (size_t)row*HH;
    float v[4];
    float s = 0.f, sq = 0.f;
#pragma unroll
    for (int i = 0; i < 4; i++) { v[i] = xr[t + 256*i]; s += v[i]; sq += v[i]*v[i]; }
#pragma unroll
    for (int o = 16; o; o >>= 1) {
        s  += __shfl_xor_sync(0xffffffffu, s,  o);
        sq += __shfl_xor_sync(0xffffffffu, sq, o);
    }
    __shared__ float rs[8], rq[8];
    if ((t & 31) == 0) { rs[t>>5] = s; rq[t>>5] = sq; }
    __syncthreads();
    if (t < 32) {
        s  = (t < 8) ? rs[t] : 0.f;
        sq = (t < 8) ? rq[t] : 0.f;
#pragma unroll
        for (int o = 4; o; o >>= 1) {
            s  += __shfl_xor_sync(0xffffffffu, s,  o);
            sq += __shfl_xor_sync(0xffffffffu, sq, o);
        }
        if (t == 0) { rs[0] = s; rq[0] = sq; }
    }
    __syncthreads();
    float mu  = rs[0] * (1.0f/HH);
    float var = rq[0] * (1.0f/HH) - mu*mu;
    float inv = rsqrtf(var + 1e-5f);
    float* orow = out + (size_t)row*HH;
#pragma unroll
    for (int i = 0; i < 4; i++) {
        int c = t + 256*i;
        orow[c] = (v[i] - mu) * inv * w[c] + bb[c];
    }
}

// ---------------- TF32 tensor-core GEMM 128x128x16 ----------------
__global__ __launch_bounds__(256) void tf32_gemm(const float* __restrict__ A,
                                                 const float* __restrict__ B,
                                                 const float* __restrict__ bias,
                                                 float* __restrict__ C,
                                                 int M, int N, int K)
{
    __shared__ uint32_t As[16][136];   // [k][m]
    __shared__ uint32_t Bs[16][136];   // [k][n]

    int tid  = threadIdx.x;
    int lane = tid & 31, warp = tid >> 5;
    int bm = blockIdx.y << 7, bn = blockIdx.x << 7;
    int warpM = (warp >> 2) << 6;
    int warpN = (warp & 3) << 5;

    int arow = tid & 127;
    int acol = (tid >> 7) << 3;
    const float* aptr = A + (size_t)(bm + arow) * K + acol;
    int bkr  = tid >> 5;
    int bcol = lane << 2;
    const float* bptr = B + (size_t)bkr * N + bn + bcol;

    float acc[4][4][4];
#pragma unroll
    for (int mt = 0; mt < 4; mt++)
#pragma unroll
        for (int nt = 0; nt < 4; nt++)
#pragma unroll
            for (int e = 0; e < 4; e++) acc[mt][nt][e] = 0.f;

    float4 aReg[2], bReg[2];
    aReg[0] = *(const float4*)(aptr);
    aReg[1] = *(const float4*)(aptr + 4);
    bReg[0] = *(const float4*)(bptr);
    bReg[1] = *(const float4*)(bptr + (size_t)8 * N);

    {
        float av0[4] = {aReg[0].x, aReg[0].y, aReg[0].z, aReg[0].w};
        float av1[4] = {aReg[1].x, aReg[1].y, aReg[1].z, aReg[1].w};
#pragma unroll
        for (int j = 0; j < 4; j++) {
            As[acol + j][arow]     = f2tf32(av0[j]);
            As[acol + 4 + j][arow] = f2tf32(av1[j]);
        }
        Bs[bkr][bcol+0] = f2tf32(bReg[0].x); Bs[bkr][bcol+1] = f2tf32(bReg[0].y);
        Bs[bkr][bcol+2] = f2tf32(bReg[0].z); Bs[bkr][bcol+3] = f2tf32(bReg[0].w);
        Bs[bkr+8][bcol+0] = f2tf32(bReg[1].x); Bs[bkr+8][bcol+1] = f2tf32(bReg[1].y);
        Bs[bkr+8][bcol+2] = f2tf32(bReg[1].z); Bs[bkr+8][bcol+3] = f2tf32(bReg[1].w);
    }
    __syncthreads();

    for (int k0 = 0; k0 < K; k0 += 16) {
        bool more = (k0 + 16) < K;
        if (more) {
            aReg[0] = *(const float4*)(aptr + k0 + 16);
            aReg[1] = *(const float4*)(aptr + k0 + 20);
            bReg[0] = *(const float4*)(bptr + (size_t)(k0 + 16) * N);
            bReg[1] = *(const float4*)(bptr + (size_t)(k0 + 24) * N);
        }

#pragma unroll
        for (int ks = 0; ks < 2; ks++) {
            uint32_t af[4][4], bf[4][2];
            int kr = ks*8 + (lane & 3);
            int am = warpM + (lane >> 2);
#pragma unroll
            for (int mt = 0; mt < 4; mt++) {
                af[mt][0] = As[kr][am + mt*16];
                af[mt][1] = As[kr][am + mt*16 + 8];
                af[mt][2] = As[kr+4][am + mt*16];
                af[mt][3] = As[kr+4][am + mt*16 + 8];
            }
            int bn0 = warpN + (lane >> 2);
#pragma unroll
            for (int nt = 0; nt < 4; nt++) {
                bf[nt][0] = Bs[kr][bn0 + nt*8];
                bf[nt][1] = Bs[kr+4][bn0 + nt*8];
            }
#pragma unroll
            for (int mt = 0; mt < 4; mt++)
#pragma unroll
                for (int nt = 0; nt < 4; nt++)
                    mma_tf32(acc[mt][nt], af[mt], bf[nt]);
        }
        __syncthreads();

        if (more) {
            float av0[4] = {aReg[0].x, aReg[0].y, aReg[0].z, aReg[0].w};
            float av1[4] = {aReg[1].x, aReg[1].y, aReg[1].z, aReg[1].w};
#pragma unroll
            for (int j = 0; j < 4; j++) {
                As[acol + j][arow]     = f2tf32(av0[j]);
                As[acol + 4 + j][arow] = f2tf32(av1[j]);
            }
            Bs[bkr][bcol+0] = f2tf32(bReg[0].x); Bs[bkr][bcol+1] = f2tf32(bReg[0].y);
            Bs[bkr][bcol+2] = f2tf32(bReg[0].z); Bs[bkr][bcol+3] = f2tf32(bReg[0].w);
            Bs[bkr+8][bcol+0] = f2tf32(bReg[1].x); Bs[bkr+8][bcol+1] = f2tf32(bReg[1].y);
            Bs[bkr+8][bcol+2] = f2tf32(bReg[1].z); Bs[bkr+8][bcol+3] = f2tf32(bReg[1].w);
            __syncthreads();
        }
    }

#pragma unroll
    for (int mt = 0; mt < 4; mt++) {
        int row0 = bm + warpM + mt*16 + (lane >> 2);
#pragma unroll
        for (int nt = 0; nt < 4; nt++) {
            int col = bn + warpN + nt*8 + ((lane & 3) << 1);
            float b0 = bias[col], b1 = bias[col + 1];
            float2 v0 = make_float2(acc[mt][nt][0] + b0, acc[mt][nt][1] + b1);
            float2 v1 = make_float2(acc[mt][nt][2] + b0, acc[mt][nt][3] + b1);
            *(float2*)(C + (size_t)row0 * N + col)       = v0;
            *(float2*)(C + (size_t)(row0 + 8) * N + col) = v1;
        }
    }
}

// ---------------- Rotary ----------------
__global__ __launch_bounds__(256) void rotary_kernel(float* __restrict__ qkv)
{
    int idx = blockIdx.x * blockDim.x + threadIdx.x;
    int d   = idx & 31;
    int h   = (idx >> 5) & (NHH - 1);
    int row = idx >> 9;
    int pos = row & (SS - 1);

    const float k = 0.28782313662425575f;   // ln(10000)/32
    float invf = expf(-k * (float)d);
    float fr = (float)pos * invf;
    float c = cosf(fr), sn = sinf(fr);

    float* qp = qkv + (size_t)row * H3 + h * HD;
    float* kp = qp + HH;

    float x1 = qp[d], x2 = qp[d + 32];
    qp[d]      = x1 * c - x2 * sn;
    qp[d + 32] = x2 * c + x1 * sn;

    x1 = kp[d]; x2 = kp[d + 32];
    kp[d]      = x1 * c - x2 * sn;
    kp[d + 32] = x2 * c + x1 * sn;
}

// ---------------- Flash attention, tf32 tensor cores ----------------
// 64 q rows x 1 head per block, 4 warps (16 q rows each), 32-key tiles.
// K: single tf32, column-interleaved so each QK B-fragment = one uint2 LDS.
// V: single tf32, [key][dim] stride-72 (conflict-free scalar frag loads).
__global__ __launch_bounds__(128, 3) void attn_tc_kernel(const float* __restrict__ qkv,
                                                         const int* __restrict__ mask,
                                                         float* __restrict__ ctx)
{
    __shared__ __align__(16) uint32_t KsI[32][72];  // tf32, interleaved cols
    __shared__ __align__(16) uint32_t VsT[32][72];  // tf32, [key][dim]
    __shared__ float Bias[32];

    int qb = blockIdx.x, h = blockIdx.y, b = blockIdx.z;
    int tid = threadIdx.x, w = tid >> 5, lane = tid & 31;
    int gq = lane >> 2, tq = lane & 3;

    // Q fragments: pre-scaled, rounded to tf32 once
    const float* qbase = qkv + ((size_t)(b*SS) + qb*64 + w*16) * H3 + h*HD;
    uint32_t qf[8][4];
#pragma unroll
    for (int j = 0; j < 8; j++) {
        const float* q0 = qbase + (size_t)gq*H3     + j*8 + tq;
        const float* q1 = qbase + (size_t)(gq+8)*H3 + j*8 + tq;
        qf[j][0] = f2tf32(q0[0] * 0.125f);
        qf[j][1] = f2tf32(q1[0] * 0.125f);
        qf[j][2] = f2tf32(q0[4] * 0.125f);
        qf[j][3] = f2tf32(q1[4] * 0.125f);
    }

    float o[8][4];
#pragma unroll
    for (int nt = 0; nt < 8; nt++)
#pragma unroll
        for (int e = 0; e < 4; e++) o[nt][e] = 0.f;
    float m0 = -1e30f, m1 = -1e30f, l0 = 0.f, l1 = 0.f;

    int row0 = qb*64 + w*16 + gq;
    int ntiles = 2*qb + 2;

    // loader coords: thread handles key r, dims c..c+3
    int lr = tid >> 4, lc = (tid & 15) << 2;
    int lj0 = lc >> 3, lt0h = (lc & 7) >> 2;   // K interleave targets

    for (int kt = 0; kt < ntiles; kt++) {
        __syncthreads();
        const float* kb = qkv + ((size_t)(b*SS) + kt*32) * H3 + HH + h*HD;
        const float* vb = kb + HH;
#pragma unroll
        for (int it = 0; it < 4; it++) {
            int r = lr + it*8;
            float4 kv = *(const float4*)(kb + (size_t)r*H3 + lc);
            float4 vv = *(const float4*)(vb + (size_t)r*H3 + lc);
            // K: interleaved columns  d=j*8+t -> j*8 + (t&3)*2 + (t>>2)
            KsI[r][lj0*8 + 0 + lt0h] = f2tf32(kv.x);
            KsI[r][lj0*8 + 2 + lt0h] = f2tf32(kv.y);
            KsI[r][lj0*8 + 4 + lt0h] = f2tf32(kv.z);
            KsI[r][lj0*8 + 6 + lt0h] = f2tf32(kv.w);
            uint4 vt;
            vt.x = f2tf32(vv.x); vt.y = f2tf32(vv.y);
            vt.z = f2tf32(vv.z); vt.w = f2tf32(vv.w);
            *(uint4*)&VsT[r][lc] = vt;
        }
        if (tid < 32)
            Bias[tid] = (1.0f - (float)mask[b*SS + kt*32 + tid]) * -10000.0f;
        __syncthreads();

        // ---- S = Q K^T (single tf32 both sides, 1 MMA per (j,nt)) ----
        float sc[4][4];
#pragma unroll
        for (int nt = 0; nt < 4; nt++)
#pragma unroll
            for (int e = 0; e < 4; e++) sc[nt][e] = 0.f;

#pragma unroll
        for (int j = 0; j < 8; j++) {
#pragma unroll
            for (int nt = 0; nt < 4; nt++) {
                uint2 kk = *(const uint2*)&KsI[nt*8 + gq][j*8 + 2*tq];
                uint32_t bh[2] = {kk.x, kk.y};
                mma_tf32(sc[nt], qf[j], bh);
            }
        }

        // ---- bias + causal mask ----
#pragma unroll
        for (int nt = 0; nt < 4; nt++) {
            int k0 = kt*32 + nt*8 + 2*tq;
            float bs0 = Bias[nt*8 + 2*tq], bs1 = Bias[nt*8 + 2*tq + 1];
            sc[nt][0] += bs0; sc[nt][1] += bs1;
            sc[nt][2] += bs0; sc[nt][3] += bs1;
            if (k0     > row0)     sc[nt][0] = -10000.0f;
            if (k0 + 1 > row0)     sc[nt][1] = -10000.0f;
            if (k0     > row0 + 8) sc[nt][2] = -10000.0f;
            if (k0 + 1 > row0 + 8) sc[nt][3] = -10000.0f;
        }

        // ---- online softmax ----
        float tm0 = -1e30f, tm1 = -1e30f;
#pragma unroll
        for (int nt = 0; nt < 4; nt++) {
            tm0 = fmaxf(tm0, fmaxf(sc[nt][0], sc[nt][1]));
            tm1 = fmaxf(tm1, fmaxf(sc[nt][2], sc[nt][3]));
        }
        tm0 = fmaxf(tm0, __shfl_xor_sync(0xffffffffu, tm0, 1));
        tm0 = fmaxf(tm0, __shfl_xor_sync(0xffffffffu, tm0, 2));
        tm1 = fmaxf(tm1, __shfl_xor_sync(0xffffffffu, tm1, 1));
        tm1 = fmaxf(tm1, __shfl_xor_sync(0xffffffffu, tm1, 2));

        float nm0 = fmaxf(m0, tm0), nm1 = fmaxf(m1, tm1);
        float c0 = __expf(m0 - nm0), c1 = __expf(m1 - nm1);
        m0 = nm0; m1 = nm1;

        float s0 = 0.f, s1 = 0.f;
#pragma unroll
        for (int nt = 0; nt < 4; nt++) {
            sc[nt][0] = __expf(sc[nt][0] - nm0); s0 += sc[nt][0];
            sc[nt][1] = __expf(sc[nt][1] - nm0); s0 += sc[nt][1];
            sc[nt][2] = __expf(sc[nt][2] - nm1); s1 += sc[nt][2];
            sc[nt][3] = __expf(sc[nt][3] - nm1); s1 += sc[nt][3];
        }
        s0 += __shfl_xor_sync(0xffffffffu, s0, 1);
        s0 += __shfl_xor_sync(0xffffffffu, s0, 2);
        s1 += __shfl_xor_sync(0xffffffffu, s1, 1);
        s1 += __shfl_xor_sync(0xffffffffu, s1, 2);
        l0 = l0*c0 + s0;
        l1 = l1*c1 + s1;

#pragma unroll
        for (int nt = 0; nt < 8; nt++) {
            o[nt][0] *= c0; o[nt][1] *= c0;
            o[nt][2] *= c1; o[nt][3] *= c1;
        }

        // ---- O += P V (P layout fix via quad shuffles; V single tf32) ----
        uint32_t src0 = (lane & ~3u) | ((uint32_t)tq >> 1);
        uint32_t src1 = src0 | 2u;
        bool odd = tq & 1;
#pragma unroll
        for (int c = 0; c < 4; c++) {
            float v00 = __shfl_sync(0xffffffffu, sc[c][0], src0);
            float v01 = __shfl_sync(0xffffffffu, sc[c][1], src0);
            float v10 = __shfl_sync(0xffffffffu, sc[c][2], src0);
            float v11 = __shfl_sync(0xffffffffu, sc[c][3], src0);
            float w00 = __shfl_sync(0xffffffffu, sc[c][0], src1);
            float w01 = __shfl_sync(0xffffffffu, sc[c][1], src1);
            float w10 = __shfl_sync(0xffffffffu, sc[c][2], src1);
            float w11 = __shfl_sync(0xffffffffu, sc[c][3], src1);
            uint32_t a[4];
            a[0] = f2tf32(odd ? v01 : v00);
            a[1] = f2tf32(odd ? v11 : v10);
            a[2] = f2tf32(odd ? w01 : w00);
            a[3] = f2tf32(odd ? w11 : w10);
#pragma unroll
            for (int nt = 0; nt < 8; nt++) {
                uint32_t bv[2];
                bv[0] = VsT[c*8 + tq][nt*8 + gq];
                bv[1] = VsT[c*8 + 4 + tq][nt*8 + gq];
                mma_tf32(o[nt], a, bv);
            }
        }
    }

    // ---- epilogue ----
    float inv0 = 1.0f / l0, inv1 = 1.0f / l1;
    float* cb = ctx + ((size_t)(b*SS) + qb*64 + w*16) * HH + h*HD;
#pragma unroll
    for (int nt = 0; nt < 8; nt++) {
        float2 u0 = make_float2(o[nt][0]*inv0, o[nt][1]*inv0);
        float2 u1 = make_float2(o[nt][2]*inv1, o[nt][3]*inv1);
        *(float2*)(cb + (size_t)gq*HH      + nt*8 + 2*tq) = u0;
        *(float2*)(cb + (size_t)(gq+8)*HH  + nt*8 + 2*tq) = u1;
    }
}

// ---------------- launch ----------------
extern "C" void kernel_launch(void* const* d_in, const int* in_sizes, int n_in,
                              void* d_out, int out_size)
{
    const float* x     = (const float*)d_in[0];
    const int*   maskp = (const int*)  d_in[1];
    const float* nw    = (const float*)d_in[2];
    const float* nb    = (const float*)d_in[3];
    const float* qkvw  = (const float*)d_in[4];
    const float* qkvb  = (const float*)d_in[5];
    const float* ow    = (const float*)d_in[6];
    const float* ob    = (const float*)d_in[7];
    float* out = (float*)d_out;

    float *xn, *qkvB, *ctx;
    cudaGetSymbolAddress((void**)&xn,   g_xn);
    cudaGetSymbolAddress((void**)&qkvB, g_qkv);
    cudaGetSymbolAddress((void**)&ctx,  g_ctx);

    ln_kernel<<<BS, 256>>>(x, nw, nb, xn);
    tf32_gemm<<<dim3(H3/128, BS/128), 256>>>(xn, qkvw, qkvb, qkvB, BS, H3, HH);
    rotary_kernel<<<(BS*NHH*32)/256, 256>>>(qkvB);
    attn_tc_kernel<<<dim3(SS/64, NHH, BB), 128>>>(qkvB, maskp, ctx);
    tf32_gemm<<<dim3(HH/128, BS/128), 256>>>(ctx, ow, ob, out, BS, HH, HH);
}

// round 6
// speedup vs baseline: 4.7654x; 1.0259x over previous
#include <cuda_runtime.h>
#include <math.h>
#include <stdint.h>

#define BB 2
#define SS 2048
#define HH 1024
#define NHH 16
#define HD 64
#define BS (BB*SS)     /* 4096 rows */
#define H3 (3*HH)      /* 3072 */

// ---------------- scratch (no allocations allowed) ----------------
__device__ float g_xn [BS*HH];   // 16 MiB
__device__ float g_qkv[BS*H3];   // 48 MiB
__device__ float g_ctx[BS*HH];   // 16 MiB

// ---------------- helpers ----------------
__device__ __forceinline__ uint32_t f2tf32(float f) {
    uint32_t u;
    asm("cvt.rna.tf32.f32 %0, %1;" : "=r"(u) : "f"(f));
    return u;
}
__device__ __forceinline__ void mma_tf32(float* c, const uint32_t* a, const uint32_t* b) {
    asm volatile("mma.sync.aligned.m16n8k8.row.col.f32.tf32.tf32.f32 "
        "{%0,%1,%2,%3}, {%4,%5,%6,%7}, {%8,%9}, {%0,%1,%2,%3};"
        : "+f"(c[0]), "+f"(c[1]), "+f"(c[2]), "+f"(c[3])
        : "r"(a[0]), "r"(a[1]), "r"(a[2]), "r"(a[3]), "r"(b[0]), "r"(b[1]));
}

// ---------------- LayerNorm ----------------
__global__ __launch_bounds__(256) void ln_kernel(const float* __restrict__ x,
                                                 const float* __restrict__ w,
                                                 const float* __restrict__ bb,
                                                 float* __restrict__ out)
{
    int row = blockIdx.x;
    int t = threadIdx.x;
    const float* xr = x + (size_t)row*HH;
    float v[4];
    float s = 0.f, sq = 0.f;
#pragma unroll
    for (int i = 0; i < 4; i++) { v[i] = xr[t + 256*i]; s += v[i]; sq += v[i]*v[i]; }
#pragma unroll
    for (int o = 16; o; o >>= 1) {
        s  += __shfl_xor_sync(0xffffffffu, s,  o);
        sq += __shfl_xor_sync(0xffffffffu, sq, o);
    }
    __shared__ float rs[8], rq[8];
    if ((t & 31) == 0) { rs[t>>5] = s; rq[t>>5] = sq; }
    __syncthreads();
    if (t < 32) {
        s  = (t < 8) ? rs[t] : 0.f;
        sq = (t < 8) ? rq[t] : 0.f;
#pragma unroll
        for (int o = 4; o; o >>= 1) {
            s  += __shfl_xor_sync(0xffffffffu, s,  o);
            sq += __shfl_xor_sync(0xffffffffu, sq, o);
        }
        if (t == 0) { rs[0] = s; rq[0] = sq; }
    }
    __syncthreads();
    float mu  = rs[0] * (1.0f/HH);
    float var = rq[0] * (1.0f/HH) - mu*mu;
    float inv = rsqrtf(var + 1e-5f);
    float* orow = out + (size_t)row*HH;
#pragma unroll
    for (int i = 0; i < 4; i++) {
        int c = t + 256*i;
        orow[c] = (v[i] - mu) * inv * w[c] + bb[c];
    }
}

// ---------------- TF32 tensor-core GEMM 128x128x16 ----------------
__global__ __launch_bounds__(256) void tf32_gemm(const float* __restrict__ A,
                                                 const float* __restrict__ B,
                                                 const float* __restrict__ bias,
                                                 float* __restrict__ C,
                                                 int M, int N, int K)
{
    __shared__ uint32_t As[16][136];   // [k][m]
    __shared__ uint32_t Bs[16][136];   // [k][n]

    int tid  = threadIdx.x;
    int lane = tid & 31, warp = tid >> 5;
    int bm = blockIdx.y << 7, bn = blockIdx.x << 7;
    int warpM = (warp >> 2) << 6;
    int warpN = (warp & 3) << 5;

    int arow = tid & 127;
    int acol = (tid >> 7) << 3;
    const float* aptr = A + (size_t)(bm + arow) * K + acol;
    int bkr  = tid >> 5;
    int bcol = lane << 2;
    const float* bptr = B + (size_t)bkr * N + bn + bcol;

    float acc[4][4][4];
#pragma unroll
    for (int mt = 0; mt < 4; mt++)
#pragma unroll
        for (int nt = 0; nt < 4; nt++)
#pragma unroll
            for (int e = 0; e < 4; e++) acc[mt][nt][e] = 0.f;

    float4 aReg[2], bReg[2];
    aReg[0] = *(const float4*)(aptr);
    aReg[1] = *(const float4*)(aptr + 4);
    bReg[0] = *(const float4*)(bptr);
    bReg[1] = *(const float4*)(bptr + (size_t)8 * N);

    {
        float av0[4] = {aReg[0].x, aReg[0].y, aReg[0].z, aReg[0].w};
        float av1[4] = {aReg[1].x, aReg[1].y, aReg[1].z, aReg[1].w};
#pragma unroll
        for (int j = 0; j < 4; j++) {
            As[acol + j][arow]     = f2tf32(av0[j]);
            As[acol + 4 + j][arow] = f2tf32(av1[j]);
        }
        Bs[bkr][bcol+0] = f2tf32(bReg[0].x); Bs[bkr][bcol+1] = f2tf32(bReg[0].y);
        Bs[bkr][bcol+2] = f2tf32(bReg[0].z); Bs[bkr][bcol+3] = f2tf32(bReg[0].w);
        Bs[bkr+8][bcol+0] = f2tf32(bReg[1].x); Bs[bkr+8][bcol+1] = f2tf32(bReg[1].y);
        Bs[bkr+8][bcol+2] = f2tf32(bReg[1].z); Bs[bkr+8][bcol+3] = f2tf32(bReg[1].w);
    }
    __syncthreads();

    for (int k0 = 0; k0 < K; k0 += 16) {
        bool more = (k0 + 16) < K;
        if (more) {
            aReg[0] = *(const float4*)(aptr + k0 + 16);
            aReg[1] = *(const float4*)(aptr + k0 + 20);
            bReg[0] = *(const float4*)(bptr + (size_t)(k0 + 16) * N);
            bReg[1] = *(const float4*)(bptr + (size_t)(k0 + 24) * N);
        }

#pragma unroll
        for (int ks = 0; ks < 2; ks++) {
            uint32_t af[4][4], bf[4][2];
            int kr = ks*8 + (lane & 3);
            int am = warpM + (lane >> 2);
#pragma unroll
            for (int mt = 0; mt < 4; mt++) {
                af[mt][0] = As[kr][am + mt*16];
                af[mt][1] = As[kr][am + mt*16 + 8];
                af[mt][2] = As[kr+4][am + mt*16];
                af[mt][3] = As[kr+4][am + mt*16 + 8];
            }
            int bn0 = warpN + (lane >> 2);
#pragma unroll
            for (int nt = 0; nt < 4; nt++) {
                bf[nt][0] = Bs[kr][bn0 + nt*8];
                bf[nt][1] = Bs[kr+4][bn0 + nt*8];
            }
#pragma unroll
            for (int mt = 0; mt < 4; mt++)
#pragma unroll
                for (int nt = 0; nt < 4; nt++)
                    mma_tf32(acc[mt][nt], af[mt], bf[nt]);
        }
        __syncthreads();

        if (more) {
            float av0[4] = {aReg[0].x, aReg[0].y, aReg[0].z, aReg[0].w};
            float av1[4] = {aReg[1].x, aReg[1].y, aReg[1].z, aReg[1].w};
#pragma unroll
            for (int j = 0; j < 4; j++) {
                As[acol + j][arow]     = f2tf32(av0[j]);
                As[acol + 4 + j][arow] = f2tf32(av1[j]);
            }
            Bs[bkr][bcol+0] = f2tf32(bReg[0].x); Bs[bkr][bcol+1] = f2tf32(bReg[0].y);
            Bs[bkr][bcol+2] = f2tf32(bReg[0].z); Bs[bkr][bcol+3] = f2tf32(bReg[0].w);
            Bs[bkr+8][bcol+0] = f2tf32(bReg[1].x); Bs[bkr+8][bcol+1] = f2tf32(bReg[1].y);
            Bs[bkr+8][bcol+2] = f2tf32(bReg[1].z); Bs[bkr+8][bcol+3] = f2tf32(bReg[1].w);
            __syncthreads();
        }
    }

#pragma unroll
    for (int mt = 0; mt < 4; mt++) {
        int row0 = bm + warpM + mt*16 + (lane >> 2);
#pragma unroll
        for (int nt = 0; nt < 4; nt++) {
            int col = bn + warpN + nt*8 + ((lane & 3) << 1);
            float b0 = bias[col], b1 = bias[col + 1];
            float2 v0 = make_float2(acc[mt][nt][0] + b0, acc[mt][nt][1] + b1);
            float2 v1 = make_float2(acc[mt][nt][2] + b0, acc[mt][nt][3] + b1);
            *(float2*)(C + (size_t)row0 * N + col)       = v0;
            *(float2*)(C + (size_t)(row0 + 8) * N + col) = v1;
        }
    }
}

// ---------------- Rotary ----------------
__global__ __launch_bounds__(256) void rotary_kernel(float* __restrict__ qkv)
{
    int idx = blockIdx.x * blockDim.x + threadIdx.x;
    int d   = idx & 31;
    int h   = (idx >> 5) & (NHH - 1);
    int row = idx >> 9;
    int pos = row & (SS - 1);

    const float k = 0.28782313662425575f;   // ln(10000)/32
    float invf = expf(-k * (float)d);
    float fr = (float)pos * invf;
    float c = cosf(fr), sn = sinf(fr);

    float* qp = qkv + (size_t)row * H3 + h * HD;
    float* kp = qp + HH;

    float x1 = qp[d], x2 = qp[d + 32];
    qp[d]      = x1 * c - x2 * sn;
    qp[d + 32] = x2 * c + x1 * sn;

    x1 = kp[d]; x2 = kp[d + 32];
    kp[d]      = x1 * c - x2 * sn;
    kp[d + 32] = x2 * c + x1 * sn;
}

// ---------------- Flash attention, tf32 tensor cores, double-buffered ----------------
// 64 q rows x 1 head per block, 4 warps (16 q rows each), 32-key tiles.
// K: single tf32, column-interleaved (QK B-frag = one uint2 LDS).
// V: single tf32, [key][dim] stride-72.
// Double-buffered smem; next tile's LDGs issued before current compute;
// ONE __syncthreads per tile.
__global__ __launch_bounds__(128, 3) void attn_tc_kernel(const float* __restrict__ qkv,
                                                         const int* __restrict__ mask,
                                                         float* __restrict__ ctx)
{
    __shared__ __align__(16) uint32_t KsI[2][32][72];  // tf32, interleaved cols
    __shared__ __align__(16) uint32_t VsT[2][32][72];  // tf32, [key][dim]
    __shared__ float Bias[2][32];

    int qb = blockIdx.x, h = blockIdx.y, b = blockIdx.z;
    int tid = threadIdx.x, w = tid >> 5, lane = tid & 31;
    int gq = lane >> 2, tq = lane & 3;

    // Q fragments: pre-scaled, rounded to tf32 once
    const float* qbase = qkv + ((size_t)(b*SS) + qb*64 + w*16) * H3 + h*HD;
    uint32_t qf[8][4];
#pragma unroll
    for (int j = 0; j < 8; j++) {
        const float* q0 = qbase + (size_t)gq*H3     + j*8 + tq;
        const float* q1 = qbase + (size_t)(gq+8)*H3 + j*8 + tq;
        qf[j][0] = f2tf32(q0[0] * 0.125f);
        qf[j][1] = f2tf32(q1[0] * 0.125f);
        qf[j][2] = f2tf32(q0[4] * 0.125f);
        qf[j][3] = f2tf32(q1[4] * 0.125f);
    }

    float o[8][4];
#pragma unroll
    for (int nt = 0; nt < 8; nt++)
#pragma unroll
        for (int e = 0; e < 4; e++) o[nt][e] = 0.f;
    float m0 = -1e30f, m1 = -1e30f, l0 = 0.f, l1 = 0.f;

    int row0 = qb*64 + w*16 + gq;
    int ntiles = 2*qb + 2;

    // loader coords: thread handles key rows lr+8*it, dims lc..lc+3
    int lr = tid >> 4, lc = (tid & 15) << 2;
    int lj0 = lc >> 3, lt0h = (lc & 7) >> 2;   // K interleave targets

    float4 kreg[4], vreg[4];
    float  breg = 0.f;

    const float* kbase0 = qkv + (size_t)(b*SS) * H3 + HH + h*HD;

    // ---- prologue: load tile 0 ----
    {
        const float* kb = kbase0;
        const float* vb = kb + HH;
#pragma unroll
        for (int it = 0; it < 4; it++) {
            int r = lr + it*8;
            kreg[it] = *(const float4*)(kb + (size_t)r*H3 + lc);
            vreg[it] = *(const float4*)(vb + (size_t)r*H3 + lc);
        }
        if (tid < 32) breg = (1.0f - (float)mask[b*SS + tid]) * -10000.0f;
#pragma unroll
        for (int it = 0; it < 4; it++) {
            int r = lr + it*8;
            KsI[0][r][lj0*8 + 0 + lt0h] = f2tf32(kreg[it].x);
            KsI[0][r][lj0*8 + 2 + lt0h] = f2tf32(kreg[it].y);
            KsI[0][r][lj0*8 + 4 + lt0h] = f2tf32(kreg[it].z);
            KsI[0][r][lj0*8 + 6 + lt0h] = f2tf32(kreg[it].w);
            uint4 vt;
            vt.x = f2tf32(vreg[it].x); vt.y = f2tf32(vreg[it].y);
            vt.z = f2tf32(vreg[it].z); vt.w = f2tf32(vreg[it].w);
            *(uint4*)&VsT[0][r][lc] = vt;
        }
        if (tid < 32) Bias[0][tid] = breg;
    }
    __syncthreads();

    for (int kt = 0; kt < ntiles; kt++) {
        int buf = kt & 1;
        bool more = (kt + 1) < ntiles;

        // ---- issue next tile's global loads (hidden behind compute) ----
        if (more) {
            const float* kb = kbase0 + (size_t)((kt+1)*32) * H3;
            const float* vb = kb + HH;
#pragma unroll
            for (int it = 0; it < 4; it++) {
                int r = lr + it*8;
                kreg[it] = *(const float4*)(kb + (size_t)r*H3 + lc);
                vreg[it] = *(const float4*)(vb + (size_t)r*H3 + lc);
            }
            if (tid < 32) breg = (1.0f - (float)mask[b*SS + (kt+1)*32 + tid]) * -10000.0f;
        }

        // ---- S = Q K^T ----
        float sc[4][4];
#pragma unroll
        for (int nt = 0; nt < 4; nt++)
#pragma unroll
            for (int e = 0; e < 4; e++) sc[nt][e] = 0.f;

#pragma unroll
        for (int j = 0; j < 8; j++) {
#pragma unroll
            for (int nt = 0; nt < 4; nt++) {
                uint2 kk = *(const uint2*)&KsI[buf][nt*8 + gq][j*8 + 2*tq];
                uint32_t bh[2] = {kk.x, kk.y};
                mma_tf32(sc[nt], qf[j], bh);
            }
        }

        // ---- bias + causal mask ----
#pragma unroll
        for (int nt = 0; nt < 4; nt++) {
            int k0 = kt*32 + nt*8 + 2*tq;
            float bs0 = Bias[buf][nt*8 + 2*tq], bs1 = Bias[buf][nt*8 + 2*tq + 1];
            sc[nt][0] += bs0; sc[nt][1] += bs1;
            sc[nt][2] += bs0; sc[nt][3] += bs1;
            if (k0     > row0)     sc[nt][0] = -10000.0f;
            if (k0 + 1 > row0)     sc[nt][1] = -10000.0f;
            if (k0     > row0 + 8) sc[nt][2] = -10000.0f;
            if (k0 + 1 > row0 + 8) sc[nt][3] = -10000.0f;
        }

        // ---- online softmax ----
        float tm0 = -1e30f, tm1 = -1e30f;
#pragma unroll
        for (int nt = 0; nt < 4; nt++) {
            tm0 = fmaxf(tm0, fmaxf(sc[nt][0], sc[nt][1]));
            tm1 = fmaxf(tm1, fmaxf(sc[nt][2], sc[nt][3]));
        }
        tm0 = fmaxf(tm0, __shfl_xor_sync(0xffffffffu, tm0, 1));
        tm0 = fmaxf(tm0, __shfl_xor_sync(0xffffffffu, tm0, 2));
        tm1 = fmaxf(tm1, __shfl_xor_sync(0xffffffffu, tm1, 1));
        tm1 = fmaxf(tm1, __shfl_xor_sync(0xffffffffu, tm1, 2));

        float nm0 = fmaxf(m0, tm0), nm1 = fmaxf(m1, tm1);
        float c0 = __expf(m0 - nm0), c1 = __expf(m1 - nm1);
        m0 = nm0; m1 = nm1;

        float s0 = 0.f, s1 = 0.f;
#pragma unroll
        for (int nt = 0; nt < 4; nt++) {
            sc[nt][0] = __expf(sc[nt][0] - nm0); s0 += sc[nt][0];
            sc[nt][1] = __expf(sc[nt][1] - nm0); s0 += sc[nt][1];
            sc[nt][2] = __expf(sc[nt][2] - nm1); s1 += sc[nt][2];
            sc[nt][3] = __expf(sc[nt][3] - nm1); s1 += sc[nt][3];
        }
        s0 += __shfl_xor_sync(0xffffffffu, s0, 1);
        s0 += __shfl_xor_sync(0xffffffffu, s0, 2);
        s1 += __shfl_xor_sync(0xffffffffu, s1, 1);
        s1 += __shfl_xor_sync(0xffffffffu, s1, 2);
        l0 = l0*c0 + s0;
        l1 = l1*c1 + s1;

#pragma unroll
        for (int nt = 0; nt < 8; nt++) {
            o[nt][0] *= c0; o[nt][1] *= c0;
            o[nt][2] *= c1; o[nt][3] *= c1;
        }

        // ---- O += P V (P layout fix via quad shuffles; V single tf32) ----
        uint32_t src0 = (lane & ~3u) | ((uint32_t)tq >> 1);
        uint32_t src1 = src0 | 2u;
        bool odd = tq & 1;
#pragma unroll
        for (int c = 0; c < 4; c++) {
            float v00 = __shfl_sync(0xffffffffu, sc[c][0], src0);
            float v01 = __shfl_sync(0xffffffffu, sc[c][1], src0);
            float v10 = __shfl_sync(0xffffffffu, sc[c][2], src0);
            float v11 = __shfl_sync(0xffffffffu, sc[c][3], src0);
            float w00 = __shfl_sync(0xffffffffu, sc[c][0], src1);
            float w01 = __shfl_sync(0xffffffffu, sc[c][1], src1);
            float w10 = __shfl_sync(0xffffffffu, sc[c][2], src1);
            float w11 = __shfl_sync(0xffffffffu, sc[c][3], src1);
            uint32_t a[4];
            a[0] = f2tf32(odd ? v01 : v00);
            a[1] = f2tf32(odd ? v11 : v10);
            a[2] = f2tf32(odd ? w01 : w00);
            a[3] = f2tf32(odd ? w11 : w10);
#pragma unroll
            for (int nt = 0; nt < 8; nt++) {
                uint32_t bv[2];
                bv[0] = VsT[buf][c*8 + tq][nt*8 + gq];
                bv[1] = VsT[buf][c*8 + 4 + tq][nt*8 + gq];
                mma_tf32(o[nt], a, bv);
            }
        }

        // ---- store next tile into the other buffer, one barrier per tile ----
        if (more) {
            int nb = buf ^ 1;
#pragma unroll
            for (int it = 0; it < 4; it++) {
                int r = lr + it*8;
                KsI[nb][r][lj0*8 + 0 + lt0h] = f2tf32(kreg[it].x);
                KsI[nb][r][lj0*8 + 2 + lt0h] = f2tf32(kreg[it].y);
                KsI[nb][r][lj0*8 + 4 + lt0h] = f2tf32(kreg[it].z);
                KsI[nb][r][lj0*8 + 6 + lt0h] = f2tf32(kreg[it].w);
                uint4 vt;
                vt.x = f2tf32(vreg[it].x); vt.y = f2tf32(vreg[it].y);
                vt.z = f2tf32(vreg[it].z); vt.w = f2tf32(vreg[it].w);
                *(uint4*)&VsT[nb][r][lc] = vt;
            }
            if (tid < 32) Bias[nb][tid] = breg;
        }
        __syncthreads();
    }

    // ---- epilogue ----
    float inv0 = 1.0f / l0, inv1 = 1.0f / l1;
    float* cb = ctx + ((size_t)(b*SS) + qb*64 + w*16) * HH + h*HD;
#pragma unroll
    for (int nt = 0; nt < 8; nt++) {
        float2 u0 = make_float2(o[nt][0]*inv0, o[nt][1]*inv0);
        float2 u1 = make_float2(o[nt][2]*inv1, o[nt][3]*inv1);
        *(float2*)(cb + (size_t)gq*HH      + nt*8 + 2*tq) = u0;
        *(float2*)(cb + (size_t)(gq+8)*HH  + nt*8 + 2*tq) = u1;
    }
}

// ---------------- launch ----------------
extern "C" void kernel_launch(void* const* d_in, const int* in_sizes, int n_in,
                              void* d_out, int out_size)
{
    const float* x     = (const float*)d_in[0];
    const int*   maskp = (const int*)  d_in[1];
    const float* nw    = (const float*)d_in[2];
    const float* nb    = (const float*)d_in[3];
    const float* qkvw  = (const float*)d_in[4];
    const float* qkvb  = (const float*)d_in[5];
    const float* ow    = (const float*)d_in[6];
    const float* ob    = (const float*)d_in[7];
    float* out = (float*)d_out;

    float *xn, *qkvB, *ctx;
    cudaGetSymbolAddress((void**)&xn,   g_xn);
    cudaGetSymbolAddress((void**)&qkvB, g_qkv);
    cudaGetSymbolAddress((void**)&ctx,  g_ctx);

    ln_kernel<<<BS, 256>>>(x, nw, nb, xn);
    tf32_gemm<<<dim3(H3/128, BS/128), 256>>>(xn, qkvw, qkvb, qkvB, BS, H3, HH);
    rotary_kernel<<<(BS*NHH*32)/256, 256>>>(qkvB);
    attn_tc_kernel<<<dim3(SS/64, NHH, BB), 128>>>(qkvB, maskp, ctx);
    tf32_gemm<<<dim3(HH/128, BS/128), 256>>>(ctx, ow, ob, out, BS, HH, HH);
}

// round 7
// speedup vs baseline: 4.8135x; 1.0101x over previous
#include <cuda_runtime.h>
#include <math.h>
#include <stdint.h>

#define BB 2
#define SS 2048
#define HH 1024
#define NHH 16
#define HD 64
#define BS (BB*SS)     /* 4096 rows */
#define H3 (3*HH)      /* 3072 */

// ---------------- scratch (no allocations allowed) ----------------
__device__ float g_xn [BS*HH];   // 16 MiB (tf32-rounded)
__device__ float g_qkv[BS*H3];   // 48 MiB
__device__ float g_ctx[BS*HH];   // 16 MiB (tf32-rounded)
__device__ float g_wq [HH*H3];   // 12 MiB (tf32-rounded qkvw)
__device__ float g_wo [HH*HH];   //  4 MiB (tf32-rounded ow)

// ---------------- helpers ----------------
__device__ __forceinline__ uint32_t f2tf32(float f) {
    uint32_t u;
    asm("cvt.rna.tf32.f32 %0, %1;" : "=r"(u) : "f"(f));
    return u;
}
__device__ __forceinline__ float rtf32(float f) { return __uint_as_float(f2tf32(f)); }
__device__ __forceinline__ void mma_tf32(float* c, const uint32_t* a, const uint32_t* b) {
    asm volatile("mma.sync.aligned.m16n8k8.row.col.f32.tf32.tf32.f32 "
        "{%0,%1,%2,%3}, {%4,%5,%6,%7}, {%8,%9}, {%0,%1,%2,%3};"
        : "+f"(c[0]), "+f"(c[1]), "+f"(c[2]), "+f"(c[3])
        : "r"(a[0]), "r"(a[1]), "r"(a[2]), "r"(a[3]), "r"(b[0]), "r"(b[1]));
}
__device__ __forceinline__ void cp16(uint32_t s, const void* g) {
    asm volatile("cp.async.cg.shared.global [%0], [%1], 16;" :: "r"(s), "l"(g));
}
#define CP_COMMIT asm volatile("cp.async.commit_group;")
#define CP_WAIT0  asm volatile("cp.async.wait_group 0;")

// ---------------- weight pre-rounding (fp32 -> tf32-RN bits) ----------------
__global__ __launch_bounds__(256) void round_w(const float4* __restrict__ in,
                                               float4* __restrict__ out, int n4)
{
    int i = blockIdx.x * 256 + threadIdx.x;
    if (i < n4) {
        float4 v = in[i];
        v.x = rtf32(v.x); v.y = rtf32(v.y);
        v.z = rtf32(v.z); v.w = rtf32(v.w);
        out[i] = v;
    }
}

// ---------------- LayerNorm (tf32-rounded output) ----------------
__global__ __launch_bounds__(256) void ln_kernel(const float* __restrict__ x,
                                                 const float* __restrict__ w,
                                                 const float* __restrict__ bb,
                                                 float* __restrict__ out)
{
    int row = blockIdx.x;
    int t = threadIdx.x;
    const float* xr = x + (size_t)row*HH;
    float v[4];
    float s = 0.f, sq = 0.f;
#pragma unroll
    for (int i = 0; i < 4; i++) { v[i] = xr[t + 256*i]; s += v[i]; sq += v[i]*v[i]; }
#pragma unroll
    for (int o = 16; o; o >>= 1) {
        s  += __shfl_xor_sync(0xffffffffu, s,  o);
        sq += __shfl_xor_sync(0xffffffffu, sq, o);
    }
    __shared__ float rs[8], rq[8];
    if ((t & 31) == 0) { rs[t>>5] = s; rq[t>>5] = sq; }
    __syncthreads();
    if (t < 32) {
        s  = (t < 8) ? rs[t] : 0.f;
        sq = (t < 8) ? rq[t] : 0.f;
#pragma unroll
        for (int o = 4; o; o >>= 1) {
            s  += __shfl_xor_sync(0xffffffffu, s,  o);
            sq += __shfl_xor_sync(0xffffffffu, sq, o);
        }
        if (t == 0) { rs[0] = s; rq[0] = sq; }
    }
    __syncthreads();
    float mu  = rs[0] * (1.0f/HH);
    float var = rq[0] * (1.0f/HH) - mu*mu;
    float inv = rsqrtf(var + 1e-5f);
    float* orow = out + (size_t)row*HH;
#pragma unroll
    for (int i = 0; i < 4; i++) {
        int c = t + 256*i;
        orow[c] = rtf32((v[i] - mu) * inv * w[c] + bb[c]);
    }
}

// ---------------- TF32 GEMM 128x128x16, cp.async double-buffered ----------------
// Operands MUST be pre-rounded to tf32 (RN). No conversions in the hot loop.
__global__ __launch_bounds__(256, 2) void tf32_gemm_ca(const float* __restrict__ A,
                                                       const float* __restrict__ B,
                                                       const float* __restrict__ bias,
                                                       float* __restrict__ C,
                                                       int M, int N, int K)
{
    __shared__ float As[2][128][20];   // [m][k], pad 20: conflict-free frag loads
    __shared__ float Bs[2][16][136];   // [k][n]

    int tid  = threadIdx.x;
    int lane = tid & 31, warp = tid >> 5;
    int bm = blockIdx.y << 7, bn = blockIdx.x << 7;
    int warpM = (warp >> 2) << 6;
    int warpN = (warp & 3) << 5;

    int arow = tid & 127;
    int acol = (tid >> 7) << 3;        // 0 or 8
    const float* aptr = A + (size_t)(bm + arow) * K + acol;
    int bkr  = tid >> 5;               // 0..7
    int bcol = lane << 2;
    const float* bptr = B + (size_t)bkr * N + bn + bcol;

    uint32_t sA0 = (uint32_t)__cvta_generic_to_shared(&As[0][arow][acol]);
    uint32_t sB0 = (uint32_t)__cvta_generic_to_shared(&Bs[0][bkr][bcol]);
    const uint32_t A_STG = 128*20*4;
    const uint32_t B_STG = 16*136*4;
    const uint32_t B_ROW8 = 8*136*4;

    // prologue: stage 0
    cp16(sA0,      aptr);
    cp16(sA0 + 16, aptr + 4);
    cp16(sB0,          bptr);
    cp16(sB0 + B_ROW8, bptr + (size_t)8 * N);
    CP_COMMIT;

    float acc[4][4][4];
#pragma unroll
    for (int mt = 0; mt < 4; mt++)
#pragma unroll
        for (int nt = 0; nt < 4; nt++)
#pragma unroll
            for (int e = 0; e < 4; e++) acc[mt][nt][e] = 0.f;

    int am  = warpM + (lane >> 2);
    int bn0 = warpN + (lane >> 2);

    for (int k0 = 0; k0 < K; k0 += 16) {
        CP_WAIT0;
        __syncthreads();
        int buf = (k0 >> 4) & 1;

        if (k0 + 16 < K) {
            uint32_t dA = sA0 + (uint32_t)(buf ^ 1) * A_STG;
            uint32_t dB = sB0 + (uint32_t)(buf ^ 1) * B_STG;
            const float* ap = aptr + k0 + 16;
            const float* bp = bptr + (size_t)(k0 + 16) * N;
            cp16(dA,      ap);
            cp16(dA + 16, ap + 4);
            cp16(dB,          bp);
            cp16(dB + B_ROW8, bp + (size_t)8 * N);
            CP_COMMIT;
        }

#pragma unroll
        for (int ks = 0; ks < 2; ks++) {
            int kr = ks*8 + (lane & 3);
            uint32_t af[4][4], bf[4][2];
#pragma unroll
            for (int mt = 0; mt < 4; mt++) {
                af[mt][0] = __float_as_uint(As[buf][am + mt*16    ][kr]);
                af[mt][1] = __float_as_uint(As[buf][am + mt*16 + 8][kr]);
                af[mt][2] = __float_as_uint(As[buf][am + mt*16    ][kr + 4]);
                af[mt][3] = __float_as_uint(As[buf][am + mt*16 + 8][kr + 4]);
            }
#pragma unroll
            for (int nt = 0; nt < 4; nt++) {
                bf[nt][0] = __float_as_uint(Bs[buf][kr    ][bn0 + nt*8]);
                bf[nt][1] = __float_as_uint(Bs[buf][kr + 4][bn0 + nt*8]);
            }
#pragma unroll
            for (int mt = 0; mt < 4; mt++)
#pragma unroll
                for (int nt = 0; nt < 4; nt++)
                    mma_tf32(acc[mt][nt], af[mt], bf[nt]);
        }
    }

    // epilogue
#pragma unroll
    for (int mt = 0; mt < 4; mt++) {
        int row0 = bm + warpM + mt*16 + (lane >> 2);
#pragma unroll
        for (int nt = 0; nt < 4; nt++) {
            int col = bn + warpN + nt*8 + ((lane & 3) << 1);
            float b0 = bias[col], b1 = bias[col + 1];
            float2 v0 = make_float2(acc[mt][nt][0] + b0, acc[mt][nt][1] + b1);
            float2 v1 = make_float2(acc[mt][nt][2] + b0, acc[mt][nt][3] + b1);
            *(float2*)(C + (size_t)row0 * N + col)       = v0;
            *(float2*)(C + (size_t)(row0 + 8) * N + col) = v1;
        }
    }
}

// ---------------- Rotary ----------------
__global__ __launch_bounds__(256) void rotary_kernel(float* __restrict__ qkv)
{
    int idx = blockIdx.x * blockDim.x + threadIdx.x;
    int d   = idx & 31;
    int h   = (idx >> 5) & (NHH - 1);
    int row = idx >> 9;
    int pos = row & (SS - 1);

    const float k = 0.28782313662425575f;   // ln(10000)/32
    float invf = expf(-k * (float)d);
    float fr = (float)pos * invf;
    float c = cosf(fr), sn = sinf(fr);

    float* qp = qkv + (size_t)row * H3 + h * HD;
    float* kp = qp + HH;

    float x1 = qp[d], x2 = qp[d + 32];
    qp[d]      = x1 * c - x2 * sn;
    qp[d + 32] = x2 * c + x1 * sn;

    x1 = kp[d]; x2 = kp[d + 32];
    kp[d]      = x1 * c - x2 * sn;
    kp[d + 32] = x2 * c + x1 * sn;
}

// ---------------- Flash attention, tf32 tensor cores, double-buffered ----------------
// 64 q rows x 1 head per block, 4 warps (16 q rows each), 32-key tiles.
// K: single tf32, column-interleaved (QK B-frag = one uint2 LDS).
// V: single tf32, [key][dim] stride-72.
// Deferred l-reduction: per-thread partials, one shuffle-reduce in epilogue.
// Output ctx is tf32-rounded (feeds the cp.async proj GEMM).
__global__ __launch_bounds__(128, 3) void attn_tc_kernel(const float* __restrict__ qkv,
                                                         const int* __restrict__ mask,
                                                         float* __restrict__ ctx)
{
    __shared__ __align__(16) uint32_t KsI[2][32][72];  // tf32, interleaved cols
    __shared__ __align__(16) uint32_t VsT[2][32][72];  // tf32, [key][dim]
    __shared__ float Bias[2][32];

    int qb = blockIdx.x, h = blockIdx.y, b = blockIdx.z;
    int tid = threadIdx.x, w = tid >> 5, lane = tid & 31;
    int gq = lane >> 2, tq = lane & 3;

    const float* qbase = qkv + ((size_t)(b*SS) + qb*64 + w*16) * H3 + h*HD;
    uint32_t qf[8][4];
#pragma unroll
    for (int j = 0; j < 8; j++) {
        const float* q0 = qbase + (size_t)gq*H3     + j*8 + tq;
        const float* q1 = qbase + (size_t)(gq+8)*H3 + j*8 + tq;
        qf[j][0] = f2tf32(q0[0] * 0.125f);
        qf[j][1] = f2tf32(q1[0] * 0.125f);
        qf[j][2] = f2tf32(q0[4] * 0.125f);
        qf[j][3] = f2tf32(q1[4] * 0.125f);
    }

    float o[8][4];
#pragma unroll
    for (int nt = 0; nt < 8; nt++)
#pragma unroll
        for (int e = 0; e < 4; e++) o[nt][e] = 0.f;
    float m0 = -1e30f, m1 = -1e30f, l0 = 0.f, l1 = 0.f;

    int row0 = qb*64 + w*16 + gq;
    int ntiles = 2*qb + 2;

    int lr = tid >> 4, lc = (tid & 15) << 2;
    int lj0 = lc >> 3, lt0h = (lc & 7) >> 2;

    float4 kreg[4], vreg[4];
    float  breg = 0.f;

    const float* kbase0 = qkv + (size_t)(b*SS) * H3 + HH + h*HD;

    // ---- prologue: load tile 0 ----
    {
        const float* kb = kbase0;
        const float* vb = kb + HH;
#pragma unroll
        for (int it = 0; it < 4; it++) {
            int r = lr + it*8;
            kreg[it] = *(const float4*)(kb + (size_t)r*H3 + lc);
            vreg[it] = *(const float4*)(vb + (size_t)r*H3 + lc);
        }
        if (tid < 32) breg = (1.0f - (float)mask[b*SS + tid]) * -10000.0f;
#pragma unroll
        for (int it = 0; it < 4; it++) {
            int r = lr + it*8;
            KsI[0][r][lj0*8 + 0 + lt0h] = f2tf32(kreg[it].x);
            KsI[0][r][lj0*8 + 2 + lt0h] = f2tf32(kreg[it].y);
            KsI[0][r][lj0*8 + 4 + lt0h] = f2tf32(kreg[it].z);
            KsI[0][r][lj0*8 + 6 + lt0h] = f2tf32(kreg[it].w);
            uint4 vt;
            vt.x = f2tf32(vreg[it].x); vt.y = f2tf32(vreg[it].y);
            vt.z = f2tf32(vreg[it].z); vt.w = f2tf32(vreg[it].w);
            *(uint4*)&VsT[0][r][lc] = vt;
        }
        if (tid < 32) Bias[0][tid] = breg;
    }
    __syncthreads();

    for (int kt = 0; kt < ntiles; kt++) {
        int buf = kt & 1;
        bool more = (kt + 1) < ntiles;

        if (more) {
            const float* kb = kbase0 + (size_t)((kt+1)*32) * H3;
            const float* vb = kb + HH;
#pragma unroll
            for (int it = 0; it < 4; it++) {
                int r = lr + it*8;
                kreg[it] = *(const float4*)(kb + (size_t)r*H3 + lc);
                vreg[it] = *(const float4*)(vb + (size_t)r*H3 + lc);
            }
            if (tid < 32) breg = (1.0f - (float)mask[b*SS + (kt+1)*32 + tid]) * -10000.0f;
        }

        // ---- S = Q K^T ----
        float sc[4][4];
#pragma unroll
        for (int nt = 0; nt < 4; nt++)
#pragma unroll
            for (int e = 0; e < 4; e++) sc[nt][e] = 0.f;

#pragma unroll
        for (int j = 0; j < 8; j++) {
#pragma unroll
            for (int nt = 0; nt < 4; nt++) {
                uint2 kk = *(const uint2*)&KsI[buf][nt*8 + gq][j*8 + 2*tq];
                uint32_t bh[2] = {kk.x, kk.y};
                mma_tf32(sc[nt], qf[j], bh);
            }
        }

        // ---- bias + causal mask ----
#pragma unroll
        for (int nt = 0; nt < 4; nt++) {
            int k0 = kt*32 + nt*8 + 2*tq;
            float bs0 = Bias[buf][nt*8 + 2*tq], bs1 = Bias[buf][nt*8 + 2*tq + 1];
            sc[nt][0] += bs0; sc[nt][1] += bs1;
            sc[nt][2] += bs0; sc[nt][3] += bs1;
            if (k0     > row0)     sc[nt][0] = -10000.0f;
            if (k0 + 1 > row0)     sc[nt][1] = -10000.0f;
            if (k0     > row0 + 8) sc[nt][2] = -10000.0f;
            if (k0 + 1 > row0 + 8) sc[nt][3] = -10000.0f;
        }

        // ---- online softmax (deferred l-reduction) ----
        float tm0 = -1e30f, tm1 = -1e30f;
#pragma unroll
        for (int nt = 0; nt < 4; nt++) {
            tm0 = fmaxf(tm0, fmaxf(sc[nt][0], sc[nt][1]));
            tm1 = fmaxf(tm1, fmaxf(sc[nt][2], sc[nt][3]));
        }
        tm0 = fmaxf(tm0, __shfl_xor_sync(0xffffffffu, tm0, 1));
        tm0 = fmaxf(tm0, __shfl_xor_sync(0xffffffffu, tm0, 2));
        tm1 = fmaxf(tm1, __shfl_xor_sync(0xffffffffu, tm1, 1));
        tm1 = fmaxf(tm1, __shfl_xor_sync(0xffffffffu, tm1, 2));

        float nm0 = fmaxf(m0, tm0), nm1 = fmaxf(m1, tm1);
        float c0 = __expf(m0 - nm0), c1 = __expf(m1 - nm1);
        m0 = nm0; m1 = nm1;

        float s0 = 0.f, s1 = 0.f;
#pragma unroll
        for (int nt = 0; nt < 4; nt++) {
            sc[nt][0] = __expf(sc[nt][0] - nm0); s0 += sc[nt][0];
            sc[nt][1] = __expf(sc[nt][1] - nm0); s0 += sc[nt][1];
            sc[nt][2] = __expf(sc[nt][2] - nm1); s1 += sc[nt][2];
            sc[nt][3] = __expf(sc[nt][3] - nm1); s1 += sc[nt][3];
        }
        l0 = l0*c0 + s0;   // per-thread partials; reduced once in epilogue
        l1 = l1*c1 + s1;

#pragma unroll
        for (int nt = 0; nt < 8; nt++) {
            o[nt][0] *= c0; o[nt][1] *= c0;
            o[nt][2] *= c1; o[nt][3] *= c1;
        }

        // ---- O += P V ----
        uint32_t src0 = (lane & ~3u) | ((uint32_t)tq >> 1);
        uint32_t src1 = src0 | 2u;
        bool odd = tq & 1;
#pragma unroll
        for (int c = 0; c < 4; c++) {
            float v00 = __shfl_sync(0xffffffffu, sc[c][0], src0);
            float v01 = __shfl_sync(0xffffffffu, sc[c][1], src0);
            float v10 = __shfl_sync(0xffffffffu, sc[c][2], src0);
            float v11 = __shfl_sync(0xffffffffu, sc[c][3], src0);
            float w00 = __shfl_sync(0xffffffffu, sc[c][0], src1);
            float w01 = __shfl_sync(0xffffffffu, sc[c][1], src1);
            float w10 = __shfl_sync(0xffffffffu, sc[c][2], src1);
            float w11 = __shfl_sync(0xffffffffu, sc[c][3], src1);
            uint32_t a[4];
            a[0] = f2tf32(odd ? v01 : v00);
            a[1] = f2tf32(odd ? v11 : v10);
            a[2] = f2tf32(odd ? w01 : w00);
            a[3] = f2tf32(odd ? w11 : w10);
#pragma unroll
            for (int nt = 0; nt < 8; nt++) {
                uint32_t bv[2];
                bv[0] = VsT[buf][c*8 + tq][nt*8 + gq];
                bv[1] = VsT[buf][c*8 + 4 + tq][nt*8 + gq];
                mma_tf32(o[nt], a, bv);
            }
        }

        if (more) {
            int nb = buf ^ 1;
#pragma unroll
            for (int it = 0; it < 4; it++) {
                int r = lr + it*8;
                KsI[nb][r][lj0*8 + 0 + lt0h] = f2tf32(kreg[it].x);
                KsI[nb][r][lj0*8 + 2 + lt0h] = f2tf32(kreg[it].y);
                KsI[nb][r][lj0*8 + 4 + lt0h] = f2tf32(kreg[it].z);
                KsI[nb][r][lj0*8 + 6 + lt0h] = f2tf32(kreg[it].w);
                uint4 vt;
                vt.x = f2tf32(vreg[it].x); vt.y = f2tf32(vreg[it].y);
                vt.z = f2tf32(vreg[it].z); vt.w = f2tf32(vreg[it].w);
                *(uint4*)&VsT[nb][r][lc] = vt;
            }
            if (tid < 32) Bias[nb][tid] = breg;
        }
        __syncthreads();
    }

    // ---- epilogue: reduce l partials, normalize, round to tf32, store ----
    l0 += __shfl_xor_sync(0xffffffffu, l0, 1);
    l0 += __shfl_xor_sync(0xffffffffu, l0, 2);
    l1 += __shfl_xor_sync(0xffffffffu, l1, 1);
    l1 += __shfl_xor_sync(0xffffffffu, l1, 2);
    float inv0 = 1.0f / l0, inv1 = 1.0f / l1;
    float* cb = ctx + ((size_t)(b*SS) + qb*64 + w*16) * HH + h*HD;
#pragma unroll
    for (int nt = 0; nt < 8; nt++) {
        float2 u0 = make_float2(rtf32(o[nt][0]*inv0), rtf32(o[nt][1]*inv0));
        float2 u1 = make_float2(rtf32(o[nt][2]*inv1), rtf32(o[nt][3]*inv1));
        *(float2*)(cb + (size_t)gq*HH      + nt*8 + 2*tq) = u0;
        *(float2*)(cb + (size_t)(gq+8)*HH  + nt*8 + 2*tq) = u1;
    }
}

// ---------------- launch ----------------
extern "C" void kernel_launch(void* const* d_in, const int* in_sizes, int n_in,
                              void* d_out, int out_size)
{
    const float* x     = (const float*)d_in[0];
    const int*   maskp = (const int*)  d_in[1];
    const float* nw    = (const float*)d_in[2];
    const float* nb    = (const float*)d_in[3];
    const float* qkvw  = (const float*)d_in[4];
    const float* qkvb  = (const float*)d_in[5];
    const float* ow    = (const float*)d_in[6];
    const float* ob    = (const float*)d_in[7];
    float* out = (float*)d_out;

    float *xn, *qkvB, *ctx, *wq, *wo;
    cudaGetSymbolAddress((void**)&xn,   g_xn);
    cudaGetSymbolAddress((void**)&qkvB, g_qkv);
    cudaGetSymbolAddress((void**)&ctx,  g_ctx);
    cudaGetSymbolAddress((void**)&wq,   g_wq);
    cudaGetSymbolAddress((void**)&wo,   g_wo);

    ln_kernel<<<BS, 256>>>(x, nw, nb, xn);
    round_w<<<(HH*H3/4 + 255)/256, 256>>>((const float4*)qkvw, (float4*)wq, HH*H3/4);
    round_w<<<(HH*HH/4 + 255)/256, 256>>>((const float4*)ow,   (float4*)wo, HH*HH/4);
    tf32_gemm_ca<<<dim3(H3/128, BS/128), 256>>>(xn, wq, qkvb, qkvB, BS, H3, HH);
    rotary_kernel<<<(BS*NHH*32)/256, 256>>>(qkvB);
    attn_tc_kernel<<<dim3(SS/64, NHH, BB), 128>>>(qkvB, maskp, ctx);
    tf32_gemm_ca<<<dim3(HH/128, BS/128), 256>>>(ctx, wo, ob, out, BS, HH, HH);
}

// round 8
// speedup vs baseline: 4.8151x; 1.0003x over previous
#include <cuda_runtime.h>
#include <math.h>
#include <stdint.h>

#define BB 2
#define SS 2048
#define HH 1024
#define NHH 16
#define HD 64
#define BS (BB*SS)     /* 4096 rows */
#define H3 (3*HH)      /* 3072 */

// ---------------- scratch (no allocations allowed) ----------------
__device__ float g_xn [BS*HH];   // 16 MiB (tf32-rounded)
__device__ float g_qkv[BS*H3];   // 48 MiB
__device__ float g_ctx[BS*HH];   // 16 MiB (tf32-rounded)
__device__ float g_wq [HH*H3];   // 12 MiB (tf32-rounded qkvw)
__device__ float g_wo [HH*HH];   //  4 MiB (tf32-rounded ow)

// ---------------- helpers ----------------
__device__ __forceinline__ uint32_t f2tf32(float f) {
    uint32_t u;
    asm("cvt.rna.tf32.f32 %0, %1;" : "=r"(u) : "f"(f));
    return u;
}
__device__ __forceinline__ float rtf32(float f) { return __uint_as_float(f2tf32(f)); }
__device__ __forceinline__ void mma_tf32(float* c, const uint32_t* a, const uint32_t* b) {
    asm volatile("mma.sync.aligned.m16n8k8.row.col.f32.tf32.tf32.f32 "
        "{%0,%1,%2,%3}, {%4,%5,%6,%7}, {%8,%9}, {%0,%1,%2,%3};"
        : "+f"(c[0]), "+f"(c[1]), "+f"(c[2]), "+f"(c[3])
        : "r"(a[0]), "r"(a[1]), "r"(a[2]), "r"(a[3]), "r"(b[0]), "r"(b[1]));
}
__device__ __forceinline__ void cp16(uint32_t s, const void* g) {
    asm volatile("cp.async.cg.shared.global [%0], [%1], 16;" :: "r"(s), "l"(g));
}
#define CP_COMMIT asm volatile("cp.async.commit_group;")
#define CP_WAIT0  asm volatile("cp.async.wait_group 0;")

// ---------------- weight pre-rounding (fp32 -> tf32-RN bits) ----------------
__global__ __launch_bounds__(256) void round_w(const float4* __restrict__ in,
                                               float4* __restrict__ out, int n4)
{
    int i = blockIdx.x * 256 + threadIdx.x;
    if (i < n4) {
        float4 v = in[i];
        v.x = rtf32(v.x); v.y = rtf32(v.y);
        v.z = rtf32(v.z); v.w = rtf32(v.w);
        out[i] = v;
    }
}

// ---------------- LayerNorm (tf32-rounded output) ----------------
__global__ __launch_bounds__(256) void ln_kernel(const float* __restrict__ x,
                                                 const float* __restrict__ w,
                                                 const float* __restrict__ bb,
                                                 float* __restrict__ out)
{
    int row = blockIdx.x;
    int t = threadIdx.x;
    const float* xr = x + (size_t)row*HH;
    float v[4];
    float s = 0.f, sq = 0.f;
#pragma unroll
    for (int i = 0; i < 4; i++) { v[i] = xr[t + 256*i]; s += v[i]; sq += v[i]*v[i]; }
#pragma unroll
    for (int o = 16; o; o >>= 1) {
        s  += __shfl_xor_sync(0xffffffffu, s,  o);
        sq += __shfl_xor_sync(0xffffffffu, sq, o);
    }
    __shared__ float rs[8], rq[8];
    if ((t & 31) == 0) { rs[t>>5] = s; rq[t>>5] = sq; }
    __syncthreads();
    if (t < 32) {
        s  = (t < 8) ? rs[t] : 0.f;
        sq = (t < 8) ? rq[t] : 0.f;
#pragma unroll
        for (int o = 4; o; o >>= 1) {
            s  += __shfl_xor_sync(0xffffffffu, s,  o);
            sq += __shfl_xor_sync(0xffffffffu, sq, o);
        }
        if (t == 0) { rs[0] = s; rq[0] = sq; }
    }
    __syncthreads();
    float mu  = rs[0] * (1.0f/HH);
    float var = rq[0] * (1.0f/HH) - mu*mu;
    float inv = rsqrtf(var + 1e-5f);
    float* orow = out + (size_t)row*HH;
#pragma unroll
    for (int i = 0; i < 4; i++) {
        int c = t + 256*i;
        orow[c] = rtf32((v[i] - mu) * inv * w[c] + bb[c]);
    }
}

// ---------------- TF32 GEMM 128x128x16, 4 warps x (64x64), cp.async ----------------
// Operands MUST be pre-rounded to tf32 (RN). 1.0 LDS per MMA.
__global__ __launch_bounds__(128, 2) void tf32_gemm_ca(const float* __restrict__ A,
                                                       const float* __restrict__ B,
                                                       const float* __restrict__ bias,
                                                       float* __restrict__ C,
                                                       int M, int N, int K)
{
    __shared__ float As[2][128][20];   // [m][k], pad 20: conflict-free frag loads
    __shared__ float Bs[2][16][136];   // [k][n]

    int tid  = threadIdx.x;
    int lane = tid & 31, warp = tid >> 5;
    int bm = blockIdx.y << 7, bn = blockIdx.x << 7;
    int warpM = (warp >> 1) << 6;      // 0 / 64
    int warpN = (warp & 1) << 6;       // 0 / 64

    // A: each thread owns one row (16 words = 4 cp16)
    int arow = tid;                    // 0..127
    const float* aptr = A + (size_t)(bm + arow) * K;
    // B: thread covers rows (tid>>5)+{0,4,8,12}, cols (tid&31)*4
    int bkr  = tid >> 5;               // 0..3
    int bcol = lane << 2;
    const float* bptr = B + (size_t)bkr * N + bn + bcol;

    uint32_t sA0 = (uint32_t)__cvta_generic_to_shared(&As[0][arow][0]);
    uint32_t sB0 = (uint32_t)__cvta_generic_to_shared(&Bs[0][bkr][bcol]);
    const uint32_t A_STG = 128*20*4;
    const uint32_t B_STG = 16*136*4;
    const uint32_t B_ROW4 = 4*136*4;

    // prologue: stage 0
#pragma unroll
    for (int c = 0; c < 4; c++) cp16(sA0 + c*16, aptr + c*4);
#pragma unroll
    for (int r = 0; r < 4; r++) cp16(sB0 + r*B_ROW4, bptr + (size_t)(r*4) * N);
    CP_COMMIT;

    float acc[4][8][4];
#pragma unroll
    for (int mt = 0; mt < 4; mt++)
#pragma unroll
        for (int nt = 0; nt < 8; nt++)
#pragma unroll
            for (int e = 0; e < 4; e++) acc[mt][nt][e] = 0.f;

    int am  = warpM + (lane >> 2);
    int bn0 = warpN + (lane >> 2);

    for (int k0 = 0; k0 < K; k0 += 16) {
        CP_WAIT0;
        __syncthreads();
        int buf = (k0 >> 4) & 1;

        if (k0 + 16 < K) {
            uint32_t dA = sA0 + (uint32_t)(buf ^ 1) * A_STG;
            uint32_t dB = sB0 + (uint32_t)(buf ^ 1) * B_STG;
            const float* ap = aptr + k0 + 16;
            const float* bp = bptr + (size_t)(k0 + 16) * N;
#pragma unroll
            for (int c = 0; c < 4; c++) cp16(dA + c*16, ap + c*4);
#pragma unroll
            for (int r = 0; r < 4; r++) cp16(dB + r*B_ROW4, bp + (size_t)(r*4) * N);
            CP_COMMIT;
        }

#pragma unroll
        for (int ks = 0; ks < 2; ks++) {
            int kr = ks*8 + (lane & 3);
            uint32_t af[4][4], bf[8][2];
#pragma unroll
            for (int mt = 0; mt < 4; mt++) {
                af[mt][0] = __float_as_uint(As[buf][am + mt*16    ][kr]);
                af[mt][1] = __float_as_uint(As[buf][am + mt*16 + 8][kr]);
                af[mt][2] = __float_as_uint(As[buf][am + mt*16    ][kr + 4]);
                af[mt][3] = __float_as_uint(As[buf][am + mt*16 + 8][kr + 4]);
            }
#pragma unroll
            for (int nt = 0; nt < 8; nt++) {
                bf[nt][0] = __float_as_uint(Bs[buf][kr    ][bn0 + nt*8]);
                bf[nt][1] = __float_as_uint(Bs[buf][kr + 4][bn0 + nt*8]);
            }
#pragma unroll
            for (int mt = 0; mt < 4; mt++)
#pragma unroll
                for (int nt = 0; nt < 8; nt++)
                    mma_tf32(acc[mt][nt], af[mt], bf[nt]);
        }
    }

    // epilogue
#pragma unroll
    for (int mt = 0; mt < 4; mt++) {
        int row0 = bm + warpM + mt*16 + (lane >> 2);
#pragma unroll
        for (int nt = 0; nt < 8; nt++) {
            int col = bn + warpN + nt*8 + ((lane & 3) << 1);
            float b0 = bias[col], b1 = bias[col + 1];
            float2 v0 = make_float2(acc[mt][nt][0] + b0, acc[mt][nt][1] + b1);
            float2 v1 = make_float2(acc[mt][nt][2] + b0, acc[mt][nt][3] + b1);
            *(float2*)(C + (size_t)row0 * N + col)       = v0;
            *(float2*)(C + (size_t)(row0 + 8) * N + col) = v1;
        }
    }
}

// ---------------- Rotary ----------------
__global__ __launch_bounds__(256) void rotary_kernel(float* __restrict__ qkv)
{
    int idx = blockIdx.x * blockDim.x + threadIdx.x;
    int d   = idx & 31;
    int h   = (idx >> 5) & (NHH - 1);
    int row = idx >> 9;
    int pos = row & (SS - 1);

    const float k = 0.28782313662425575f;   // ln(10000)/32
    float invf = expf(-k * (float)d);
    float fr = (float)pos * invf;
    float c = cosf(fr), sn = sinf(fr);

    float* qp = qkv + (size_t)row * H3 + h * HD;
    float* kp = qp + HH;

    float x1 = qp[d], x2 = qp[d + 32];
    qp[d]      = x1 * c - x2 * sn;
    qp[d + 32] = x2 * c + x1 * sn;

    x1 = kp[d]; x2 = kp[d + 32];
    kp[d]      = x1 * c - x2 * sn;
    kp[d + 32] = x2 * c + x1 * sn;
}

// ---------------- Flash attention, tf32 tensor cores, double-buffered ----------------
__global__ __launch_bounds__(128, 3) void attn_tc_kernel(const float* __restrict__ qkv,
                                                         const int* __restrict__ mask,
                                                         float* __restrict__ ctx)
{
    __shared__ __align__(16) uint32_t KsI[2][32][72];  // tf32, interleaved cols
    __shared__ __align__(16) uint32_t VsT[2][32][72];  // tf32, [key][dim]
    __shared__ float Bias[2][32];

    int qb = blockIdx.x, h = blockIdx.y, b = blockIdx.z;
    int tid = threadIdx.x, w = tid >> 5, lane = tid & 31;
    int gq = lane >> 2, tq = lane & 3;

    const float* qbase = qkv + ((size_t)(b*SS) + qb*64 + w*16) * H3 + h*HD;
    uint32_t qf[8][4];
#pragma unroll
    for (int j = 0; j < 8; j++) {
        const float* q0 = qbase + (size_t)gq*H3     + j*8 + tq;
        const float* q1 = qbase + (size_t)(gq+8)*H3 + j*8 + tq;
        qf[j][0] = f2tf32(q0[0] * 0.125f);
        qf[j][1] = f2tf32(q1[0] * 0.125f);
        qf[j][2] = f2tf32(q0[4] * 0.125f);
        qf[j][3] = f2tf32(q1[4] * 0.125f);
    }

    float o[8][4];
#pragma unroll
    for (int nt = 0; nt < 8; nt++)
#pragma unroll
        for (int e = 0; e < 4; e++) o[nt][e] = 0.f;
    float m0 = -1e30f, m1 = -1e30f, l0 = 0.f, l1 = 0.f;

    int row0 = qb*64 + w*16 + gq;
    int ntiles = 2*qb + 2;

    int lr = tid >> 4, lc = (tid & 15) << 2;
    int lj0 = lc >> 3, lt0h = (lc & 7) >> 2;

    float4 kreg[4], vreg[4];
    float  breg = 0.f;

    const float* kbase0 = qkv + (size_t)(b*SS) * H3 + HH + h*HD;

    // ---- prologue: load tile 0 ----
    {
        const float* kb = kbase0;
        const float* vb = kb + HH;
#pragma unroll
        for (int it = 0; it < 4; it++) {
            int r = lr + it*8;
            kreg[it] = *(const float4*)(kb + (size_t)r*H3 + lc);
            vreg[it] = *(const float4*)(vb + (size_t)r*H3 + lc);
        }
        if (tid < 32) breg = (1.0f - (float)mask[b*SS + tid]) * -10000.0f;
#pragma unroll
        for (int it = 0; it < 4; it++) {
            int r = lr + it*8;
            KsI[0][r][lj0*8 + 0 + lt0h] = f2tf32(kreg[it].x);
            KsI[0][r][lj0*8 + 2 + lt0h] = f2tf32(kreg[it].y);
            KsI[0][r][lj0*8 + 4 + lt0h] = f2tf32(kreg[it].z);
            KsI[0][r][lj0*8 + 6 + lt0h] = f2tf32(kreg[it].w);
            uint4 vt;
            vt.x = f2tf32(vreg[it].x); vt.y = f2tf32(vreg[it].y);
            vt.z = f2tf32(vreg[it].z); vt.w = f2tf32(vreg[it].w);
            *(uint4*)&VsT[0][r][lc] = vt;
        }
        if (tid < 32) Bias[0][tid] = breg;
    }
    __syncthreads();

    for (int kt = 0; kt < ntiles; kt++) {
        int buf = kt & 1;
        bool more = (kt + 1) < ntiles;

        if (more) {
            const float* kb = kbase0 + (size_t)((kt+1)*32) * H3;
            const float* vb = kb + HH;
#pragma unroll
            for (int it = 0; it < 4; it++) {
                int r = lr + it*8;
                kreg[it] = *(const float4*)(kb + (size_t)r*H3 + lc);
                vreg[it] = *(const float4*)(vb + (size_t)r*H3 + lc);
            }
            if (tid < 32) breg = (1.0f - (float)mask[b*SS + (kt+1)*32 + tid]) * -10000.0f;
        }

        // ---- S = Q K^T ----
        float sc[4][4];
#pragma unroll
        for (int nt = 0; nt < 4; nt++)
#pragma unroll
            for (int e = 0; e < 4; e++) sc[nt][e] = 0.f;

#pragma unroll
        for (int j = 0; j < 8; j++) {
#pragma unroll
            for (int nt = 0; nt < 4; nt++) {
                uint2 kk = *(const uint2*)&KsI[buf][nt*8 + gq][j*8 + 2*tq];
                uint32_t bh[2] = {kk.x, kk.y};
                mma_tf32(sc[nt], qf[j], bh);
            }
        }

        // ---- bias + causal mask ----
#pragma unroll
        for (int nt = 0; nt < 4; nt++) {
            int k0 = kt*32 + nt*8 + 2*tq;
            float bs0 = Bias[buf][nt*8 + 2*tq], bs1 = Bias[buf][nt*8 + 2*tq + 1];
            sc[nt][0] += bs0; sc[nt][1] += bs1;
            sc[nt][2] += bs0; sc[nt][3] += bs1;
            if (k0     > row0)     sc[nt][0] = -10000.0f;
            if (k0 + 1 > row0)     sc[nt][1] = -10000.0f;
            if (k0     > row0 + 8) sc[nt][2] = -10000.0f;
            if (k0 + 1 > row0 + 8) sc[nt][3] = -10000.0f;
        }

        // ---- online softmax (deferred l-reduction) ----
        float tm0 = -1e30f, tm1 = -1e30f;
#pragma unroll
        for (int nt = 0; nt < 4; nt++) {
            tm0 = fmaxf(tm0, fmaxf(sc[nt][0], sc[nt][1]));
            tm1 = fmaxf(tm1, fmaxf(sc[nt][2], sc[nt][3]));
        }
        tm0 = fmaxf(tm0, __shfl_xor_sync(0xffffffffu, tm0, 1));
        tm0 = fmaxf(tm0, __shfl_xor_sync(0xffffffffu, tm0, 2));
        tm1 = fmaxf(tm1, __shfl_xor_sync(0xffffffffu, tm1, 1));
        tm1 = fmaxf(tm1, __shfl_xor_sync(0xffffffffu, tm1, 2));

        float nm0 = fmaxf(m0, tm0), nm1 = fmaxf(m1, tm1);
        float c0 = __expf(m0 - nm0), c1 = __expf(m1 - nm1);
        m0 = nm0; m1 = nm1;

        float s0 = 0.f, s1 = 0.f;
#pragma unroll
        for (int nt = 0; nt < 4; nt++) {
            sc[nt][0] = __expf(sc[nt][0] - nm0); s0 += sc[nt][0];
            sc[nt][1] = __expf(sc[nt][1] - nm0); s0 += sc[nt][1];
            sc[nt][2] = __expf(sc[nt][2] - nm1); s1 += sc[nt][2];
            sc[nt][3] = __expf(sc[nt][3] - nm1); s1 += sc[nt][3];
        }
        l0 = l0*c0 + s0;
        l1 = l1*c1 + s1;

#pragma unroll
        for (int nt = 0; nt < 8; nt++) {
            o[nt][0] *= c0; o[nt][1] *= c0;
            o[nt][2] *= c1; o[nt][3] *= c1;
        }

        // ---- O += P V ----
        uint32_t src0 = (lane & ~3u) | ((uint32_t)tq >> 1);
        uint32_t src1 = src0 | 2u;
        bool odd = tq & 1;
#pragma unroll
        for (int c = 0; c < 4; c++) {
            float v00 = __shfl_sync(0xffffffffu, sc[c][0], src0);
            float v01 = __shfl_sync(0xffffffffu, sc[c][1], src0);
            float v10 = __shfl_sync(0xffffffffu, sc[c][2], src0);
            float v11 = __shfl_sync(0xffffffffu, sc[c][3], src0);
            float w00 = __shfl_sync(0xffffffffu, sc[c][0], src1);
            float w01 = __shfl_sync(0xffffffffu, sc[c][1], src1);
            float w10 = __shfl_sync(0xffffffffu, sc[c][2], src1);
            float w11 = __shfl_sync(0xffffffffu, sc[c][3], src1);
            uint32_t a[4];
            a[0] = f2tf32(odd ? v01 : v00);
            a[1] = f2tf32(odd ? v11 : v10);
            a[2] = f2tf32(odd ? w01 : w00);
            a[3] = f2tf32(odd ? w11 : w10);
#pragma unroll
            for (int nt = 0; nt < 8; nt++) {
                uint32_t bv[2];
                bv[0] = VsT[buf][c*8 + tq][nt*8 + gq];
                bv[1] = VsT[buf][c*8 + 4 + tq][nt*8 + gq];
                mma_tf32(o[nt], a, bv);
            }
        }

        if (more) {
            int nb = buf ^ 1;
#pragma unroll
            for (int it = 0; it < 4; it++) {
                int r = lr + it*8;
                KsI[nb][r][lj0*8 + 0 + lt0h] = f2tf32(kreg[it].x);
                KsI[nb][r][lj0*8 + 2 + lt0h] = f2tf32(kreg[it].y);
                KsI[nb][r][lj0*8 + 4 + lt0h] = f2tf32(kreg[it].z);
                KsI[nb][r][lj0*8 + 6 + lt0h] = f2tf32(kreg[it].w);
                uint4 vt;
                vt.x = f2tf32(vreg[it].x); vt.y = f2tf32(vreg[it].y);
                vt.z = f2tf32(vreg[it].z); vt.w = f2tf32(vreg[it].w);
                *(uint4*)&VsT[nb][r][lc] = vt;
            }
            if (tid < 32) Bias[nb][tid] = breg;
        }
        __syncthreads();
    }

    // ---- epilogue ----
    l0 += __shfl_xor_sync(0xffffffffu, l0, 1);
    l0 += __shfl_xor_sync(0xffffffffu, l0, 2);
    l1 += __shfl_xor_sync(0xffffffffu, l1, 1);
    l1 += __shfl_xor_sync(0xffffffffu, l1, 2);
    float inv0 = 1.0f / l0, inv1 = 1.0f / l1;
    float* cb = ctx + ((size_t)(b*SS) + qb*64 + w*16) * HH + h*HD;
#pragma unroll
    for (int nt = 0; nt < 8; nt++) {
        float2 u0 = make_float2(rtf32(o[nt][0]*inv0), rtf32(o[nt][1]*inv0));
        float2 u1 = make_float2(rtf32(o[nt][2]*inv1), rtf32(o[nt][3]*inv1));
        *(float2*)(cb + (size_t)gq*HH      + nt*8 + 2*tq) = u0;
        *(float2*)(cb + (size_t)(gq+8)*HH  + nt*8 + 2*tq) = u1;
    }
}

// ---------------- launch ----------------
extern "C" void kernel_launch(void* const* d_in, const int* in_sizes, int n_in,
                              void* d_out, int out_size)
{
    const float* x     = (const float*)d_in[0];
    const int*   maskp = (const int*)  d_in[1];
    const float* nw    = (const float*)d_in[2];
    const float* nb    = (const float*)d_in[3];
    const float* qkvw  = (const float*)d_in[4];
    const float* qkvb  = (const float*)d_in[5];
    const float* ow    = (const float*)d_in[6];
    const float* ob    = (const float*)d_in[7];
    float* out = (float*)d_out;

    float *xn, *qkvB, *ctx, *wq, *wo;
    cudaGetSymbolAddress((void**)&xn,   g_xn);
    cudaGetSymbolAddress((void**)&qkvB, g_qkv);
    cudaGetSymbolAddress((void**)&ctx,  g_ctx);
    cudaGetSymbolAddress((void**)&wq,   g_wq);
    cudaGetSymbolAddress((void**)&wo,   g_wo);

    ln_kernel<<<BS, 256>>>(x, nw, nb, xn);
    round_w<<<(HH*H3/4 + 255)/256, 256>>>((const float4*)qkvw, (float4*)wq, HH*H3/4);
    round_w<<<(HH*HH/4 + 255)/256, 256>>>((const float4*)ow,   (float4*)wo, HH*HH/4);
    tf32_gemm_ca<<<dim3(H3/128, BS/128), 128>>>(xn, wq, qkvb, qkvB, BS, H3, HH);
    rotary_kernel<<<(BS*NHH*32)/256, 256>>>(qkvB);
    attn_tc_kernel<<<dim3(SS/64, NHH, BB), 128>>>(qkvB, maskp, ctx);
    tf32_gemm_ca<<<dim3(HH/128, BS/128), 128>>>(ctx, wo, ob, out, BS, HH, HH);
}

// round 10
// speedup vs baseline: 6.1070x; 1.2683x over previous
#include <cuda_runtime.h>
#include <cuda_fp16.h>
#include <math.h>
#include <stdint.h>

#define BB 2
#define SS 2048
#define HH 1024
#define NHH 16
#define HD 64
#define BS (BB*SS)     /* 4096 rows */
#define H3 (3*HH)      /* 3072 */

// ---------------- scratch (no allocations allowed) ----------------
__device__ __half g_xn [BS*HH];   // 8 MiB (fp16)
__device__ float  g_qkv[BS*H3];   // 48 MiB
__device__ __half g_ctx[BS*HH];   // 8 MiB (fp16)
__device__ __half g_wq [HH*H3];   // 6 MiB (fp16, transposed [N][K])
__device__ __half g_wo [HH*HH];   // 2 MiB (fp16, transposed [N][K])

// ---------------- helpers ----------------
__device__ __forceinline__ uint32_t f2tf32(float f) {
    uint32_t u;
    asm("cvt.rna.tf32.f32 %0, %1;" : "=r"(u) : "f"(f));
    return u;
}
__device__ __forceinline__ void mma_tf32(float* c, const uint32_t* a, const uint32_t* b) {
    asm volatile("mma.sync.aligned.m16n8k8.row.col.f32.tf32.tf32.f32 "
        "{%0,%1,%2,%3}, {%4,%5,%6,%7}, {%8,%9}, {%0,%1,%2,%3};"
        : "+f"(c[0]), "+f"(c[1]), "+f"(c[2]), "+f"(c[3])
        : "r"(a[0]), "r"(a[1]), "r"(a[2]), "r"(a[3]), "r"(b[0]), "r"(b[1]));
}
__device__ __forceinline__ void mma_f16(float* c, const uint32_t* a, const uint32_t* b) {
    asm volatile("mma.sync.aligned.m16n8k16.row.col.f32.f16.f16.f32 "
        "{%0,%1,%2,%3}, {%4,%5,%6,%7}, {%8,%9}, {%0,%1,%2,%3};"
        : "+f"(c[0]), "+f"(c[1]), "+f"(c[2]), "+f"(c[3])
        : "r"(a[0]), "r"(a[1]), "r"(a[2]), "r"(a[3]), "r"(b[0]), "r"(b[1]));
}
__device__ __forceinline__ void cp16(uint32_t s, const void* g) {
    asm volatile("cp.async.cg.shared.global [%0], [%1], 16;" :: "r"(s), "l"(g));
}
#define CP_COMMIT asm volatile("cp.async.commit_group;")
#define CP_WAIT0  asm volatile("cp.async.wait_group 0;")
__device__ __forceinline__ uint32_t s2u(const void* p) {
    return (uint32_t)__cvta_generic_to_shared(p);
}

// ---------------- weight transpose + fp16: in[K][N] fp32 -> out[N][K] fp16 ----------------
__global__ __launch_bounds__(256) void transpose_w(const float* __restrict__ in,
                                                   __half* __restrict__ out,
                                                   int Kd, int Nd)
{
    __shared__ float t[32][33];
    int n0 = blockIdx.x << 5, k0 = blockIdx.y << 5;
    int x = threadIdx.x, y = threadIdx.y;
#pragma unroll
    for (int i = 0; i < 32; i += 8)
        t[y + i][x] = in[(size_t)(k0 + y + i) * Nd + n0 + x];
    __syncthreads();
#pragma unroll
    for (int i = 0; i < 32; i += 8)
        out[(size_t)(n0 + y + i) * Kd + k0 + x] = __float2half_rn(t[x][y + i]);
}

// ---------------- LayerNorm (fp16 output) ----------------
__global__ __launch_bounds__(256) void ln_kernel(const float* __restrict__ x,
                                                 const float* __restrict__ w,
                                                 const float* __restrict__ bb,
                                                 __half* __restrict__ out)
{
    int row = blockIdx.x;
    int t = threadIdx.x;
    const float* xr = x + (size_t)row*HH;
    float v[4];
    float s = 0.f, sq = 0.f;
#pragma unroll
    for (int i = 0; i < 4; i++) { v[i] = xr[t + 256*i]; s += v[i]; sq += v[i]*v[i]; }
#pragma unroll
    for (int o = 16; o; o >>= 1) {
        s  += __shfl_xor_sync(0xffffffffu, s,  o);
        sq += __shfl_xor_sync(0xffffffffu, sq, o);
    }
    __shared__ float rs[8], rq[8];
    if ((t & 31) == 0) { rs[t>>5] = s; rq[t>>5] = sq; }
    __syncthreads();
    if (t < 32) {
        s  = (t < 8) ? rs[t] : 0.f;
        sq = (t < 8) ? rq[t] : 0.f;
#pragma unroll
        for (int o = 4; o; o >>= 1) {
            s  += __shfl_xor_sync(0xffffffffu, s,  o);
            sq += __shfl_xor_sync(0xffffffffu, sq, o);
        }
        if (t == 0) { rs[0] = s; rq[0] = sq; }
    }
    __syncthreads();
    float mu  = rs[0] * (1.0f/HH);
    float var = rq[0] * (1.0f/HH) - mu*mu;
    float inv = rsqrtf(var + 1e-5f);
    __half* orow = out + (size_t)row*HH;
#pragma unroll
    for (int i = 0; i < 4; i++) {
        int c = t + 256*i;
        orow[c] = __float2half_rn((v[i] - mu) * inv * w[c] + bb[c]);
    }
}

// ---------------- FP16 GEMM 128x128x32, 4 warps x (64x64), cp.async ----------------
// C[M,N] = A[M,K] @ Bt[N,K]^T + bias.  A, Bt fp16 K-major.  m16n8k16 HMMA.
// Smem [row][k-pair uints], stride 20 (banks (20m+j)%32 all distinct).
__global__ __launch_bounds__(128, 2) void fp16_gemm(const __half* __restrict__ A,
                                                    const __half* __restrict__ Bt,
                                                    const float* __restrict__ bias,
                                                    float* __restrict__ C,
                                                    int M, int N, int K)
{
    __shared__ uint32_t As[2][128][20];   // 16 k-pair uints + pad 4
    __shared__ uint32_t Bs[2][128][20];

    int tid  = threadIdx.x;
    int lane = tid & 31, warp = tid >> 5;
    int bm = blockIdx.y << 7, bn = blockIdx.x << 7;
    int warpM = (warp >> 1) << 6;      // 0 / 64
    int warpN = (warp & 1) << 6;       // 0 / 64

    const __half* aRow = A  + (size_t)(bm + tid) * K;
    const __half* bRow = Bt + (size_t)(bn + tid) * K;

    uint32_t sA = s2u(&As[0][tid][0]);
    uint32_t sB = s2u(&Bs[0][tid][0]);
    const uint32_t STG = 128u * 20u * 4u;

    // prologue: chunk 0 -> buf 0  (chunk = 32 halves = 64B = 4 cp16 per row)
#pragma unroll
    for (int u = 0; u < 4; u++) {
        cp16(sA + u*16, aRow + u*8);
        cp16(sB + u*16, bRow + u*8);
    }
    CP_COMMIT;

    float acc[4][8][4];
#pragma unroll
    for (int mt = 0; mt < 4; mt++)
#pragma unroll
        for (int nt = 0; nt < 8; nt++)
#pragma unroll
            for (int e = 0; e < 4; e++) acc[mt][nt][e] = 0.f;

    int am  = warpM + (lane >> 2);
    int bn0 = warpN + (lane >> 2);
    int kq  = lane & 3;

    const int nch = K >> 5;   // chunks of 32 halves

    for (int c = 0; c < nch; c++) {
        CP_WAIT0;
        __syncthreads();
        int buf = c & 1;

        if (c + 1 < nch) {
            uint32_t dA = sA + (uint32_t)(buf ^ 1) * STG;
            uint32_t dB = sB + (uint32_t)(buf ^ 1) * STG;
            const __half* ap = aRow + (c + 1) * 32;
            const __half* bp = bRow + (c + 1) * 32;
#pragma unroll
            for (int u = 0; u < 4; u++) {
                cp16(dA + u*16, ap + u*8);
                cp16(dB + u*16, bp + u*8);
            }
            CP_COMMIT;
        }

#pragma unroll
        for (int ks = 0; ks < 2; ks++) {
            int base = ks * 8;
            uint32_t af[4][4], bf[8][2];
#pragma unroll
            for (int mt = 0; mt < 4; mt++) {
                int m = am + mt*16;
                af[mt][0] = As[buf][m    ][base + kq];
                af[mt][1] = As[buf][m + 8][base + kq];
                af[mt][2] = As[buf][m    ][base + kq + 4];
                af[mt][3] = As[buf][m + 8][base + kq + 4];
            }
#pragma unroll
            for (int nt = 0; nt < 8; nt++) {
                int n = bn0 + nt*8;
                bf[nt][0] = Bs[buf][n][base + kq];
                bf[nt][1] = Bs[buf][n][base + kq + 4];
            }
#pragma unroll
            for (int mt = 0; mt < 4; mt++)
#pragma unroll
                for (int nt = 0; nt < 8; nt++)
                    mma_f16(acc[mt][nt], af[mt], bf[nt]);
        }
    }

    // epilogue
#pragma unroll
    for (int mt = 0; mt < 4; mt++) {
        int row0 = bm + warpM + mt*16 + (lane >> 2);
#pragma unroll
        for (int nt = 0; nt < 8; nt++) {
            int col = bn + warpN + nt*8 + ((lane & 3) << 1);
            float b0 = bias[col], b1 = bias[col + 1];
            float2 v0 = make_float2(acc[mt][nt][0] + b0, acc[mt][nt][1] + b1);
            float2 v1 = make_float2(acc[mt][nt][2] + b0, acc[mt][nt][3] + b1);
            *(float2*)(C + (size_t)row0 * N + col)       = v0;
            *(float2*)(C + (size_t)(row0 + 8) * N + col) = v1;
        }
    }
}

// ---------------- Rotary ----------------
__global__ __launch_bounds__(256) void rotary_kernel(float* __restrict__ qkv)
{
    int idx = blockIdx.x * blockDim.x + threadIdx.x;
    int d   = idx & 31;
    int h   = (idx >> 5) & (NHH - 1);
    int row = idx >> 9;
    int pos = row & (SS - 1);

    const float k = 0.28782313662425575f;   // ln(10000)/32
    float invf = expf(-k * (float)d);
    float fr = (float)pos * invf;
    float c = cosf(fr), sn = sinf(fr);

    float* qp = qkv + (size_t)row * H3 + h * HD;
    float* kp = qp + HH;

    float x1 = qp[d], x2 = qp[d + 32];
    qp[d]      = x1 * c - x2 * sn;
    qp[d + 32] = x2 * c + x1 * sn;

    x1 = kp[d]; x2 = kp[d + 32];
    kp[d]      = x1 * c - x2 * sn;
    kp[d + 32] = x2 * c + x1 * sn;
}

// ---------------- Flash attention, tf32 tensor cores, double-buffered ----------------
// (unchanged from round 8 except the fp16 ctx epilogue)
__global__ __launch_bounds__(128, 3) void attn_tc_kernel(const float* __restrict__ qkv,
                                                         const int* __restrict__ mask,
                                                         __half* __restrict__ ctx)
{
    __shared__ __align__(16) uint32_t KsI[2][32][72];  // tf32, interleaved cols
    __shared__ __align__(16) uint32_t VsT[2][32][72];  // tf32, [key][dim]
    __shared__ float Bias[2][32];

    int qb = blockIdx.x, h = blockIdx.y, b = blockIdx.z;
    int tid = threadIdx.x, w = tid >> 5, lane = tid & 31;
    int gq = lane >> 2, tq = lane & 3;

    const float* qbase = qkv + ((size_t)(b*SS) + qb*64 + w*16) * H3 + h*HD;
    uint32_t qf[8][4];
#pragma unroll
    for (int j = 0; j < 8; j++) {
        const float* q0 = qbase + (size_t)gq*H3     + j*8 + tq;
        const float* q1 = qbase + (size_t)(gq+8)*H3 + j*8 + tq;
        qf[j][0] = f2tf32(q0[0] * 0.125f);
        qf[j][1] = f2tf32(q1[0] * 0.125f);
        qf[j][2] = f2tf32(q0[4] * 0.125f);
        qf[j][3] = f2tf32(q1[4] * 0.125f);
    }

    float o[8][4];
#pragma unroll
    for (int nt = 0; nt < 8; nt++)
#pragma unroll
        for (int e = 0; e < 4; e++) o[nt][e] = 0.f;
    float m0 = -1e30f, m1 = -1e30f, l0 = 0.f, l1 = 0.f;

    int row0 = qb*64 + w*16 + gq;
    int ntiles = 2*qb + 2;

    int lr = tid >> 4, lc = (tid & 15) << 2;
    int lj0 = lc >> 3, lt0h = (lc & 7) >> 2;

    float4 kreg[4], vreg[4];
    float  breg = 0.f;

    const float* kbase0 = qkv + (size_t)(b*SS) * H3 + HH + h*HD;

    {
        const float* kb = kbase0;
        const float* vb = kb + HH;
#pragma unroll
        for (int it = 0; it < 4; it++) {
            int r = lr + it*8;
            kreg[it] = *(const float4*)(kb + (size_t)r*H3 + lc);
            vreg[it] = *(const float4*)(vb + (size_t)r*H3 + lc);
        }
        if (tid < 32) breg = (1.0f - (float)mask[b*SS + tid]) * -10000.0f;
#pragma unroll
        for (int it = 0; it < 4; it++) {
            int r = lr + it*8;
            KsI[0][r][lj0*8 + 0 + lt0h] = f2tf32(kreg[it].x);
            KsI[0][r][lj0*8 + 2 + lt0h] = f2tf32(kreg[it].y);
            KsI[0][r][lj0*8 + 4 + lt0h] = f2tf32(kreg[it].z);
            KsI[0][r][lj0*8 + 6 + lt0h] = f2tf32(kreg[it].w);
            uint4 vt;
            vt.x = f2tf32(vreg[it].x); vt.y = f2tf32(vreg[it].y);
            vt.z = f2tf32(vreg[it].z); vt.w = f2tf32(vreg[it].w);
            *(uint4*)&VsT[0][r][lc] = vt;
        }
        if (tid < 32) Bias[0][tid] = breg;
    }
    __syncthreads();

    for (int kt = 0; kt < ntiles; kt++) {
        int buf = kt & 1;
        bool more = (kt + 1) < ntiles;

        if (more) {
            const float* kb = kbase0 + (size_t)((kt+1)*32) * H3;
            const float* vb = kb + HH;
#pragma unroll
            for (int it = 0; it < 4; it++) {
                int r = lr + it*8;
                kreg[it] = *(const float4*)(kb + (size_t)r*H3 + lc);
                vreg[it] = *(const float4*)(vb + (size_t)r*H3 + lc);
            }
            if (tid < 32) breg = (1.0f - (float)mask[b*SS + (kt+1)*32 + tid]) * -10000.0f;
        }

        float sc[4][4];
#pragma unroll
        for (int nt = 0; nt < 4; nt++)
#pragma unroll
            for (int e = 0; e < 4; e++) sc[nt][e] = 0.f;

#pragma unroll
        for (int j = 0; j < 8; j++) {
#pragma unroll
            for (int nt = 0; nt < 4; nt++) {
                uint2 kk = *(const uint2*)&KsI[buf][nt*8 + gq][j*8 + 2*tq];
                uint32_t bh[2] = {kk.x, kk.y};
                mma_tf32(sc[nt], qf[j], bh);
            }
        }

#pragma unroll
        for (int nt = 0; nt < 4; nt++) {
            int k0 = kt*32 + nt*8 + 2*tq;
            float bs0 = Bias[buf][nt*8 + 2*tq], bs1 = Bias[buf][nt*8 + 2*tq + 1];
            sc[nt][0] += bs0; sc[nt][1] += bs1;
            sc[nt][2] += bs0; sc[nt][3] += bs1;
            if (k0     > row0)     sc[nt][0] = -10000.0f;
            if (k0 + 1 > row0)     sc[nt][1] = -10000.0f;
            if (k0     > row0 + 8) sc[nt][2] = -10000.0f;
            if (k0 + 1 > row0 + 8) sc[nt][3] = -10000.0f;
        }

        float tm0 = -1e30f, tm1 = -1e30f;
#pragma unroll
        for (int nt = 0; nt < 4; nt++) {
            tm0 = fmaxf(tm0, fmaxf(sc[nt][0], sc[nt][1]));
            tm1 = fmaxf(tm1, fmaxf(sc[nt][2], sc[nt][3]));
        }
        tm0 = fmaxf(tm0, __shfl_xor_sync(0xffffffffu, tm0, 1));
        tm0 = fmaxf(tm0, __shfl_xor_sync(0xffffffffu, tm0, 2));
        tm1 = fmaxf(tm1, __shfl_xor_sync(0xffffffffu, tm1, 1));
        tm1 = fmaxf(tm1, __shfl_xor_sync(0xffffffffu, tm1, 2));

        float nm0 = fmaxf(m0, tm0), nm1 = fmaxf(m1, tm1);
        float c0 = __expf(m0 - nm0), c1 = __expf(m1 - nm1);
        m0 = nm0; m1 = nm1;

        float s0 = 0.f, s1 = 0.f;
#pragma unroll
        for (int nt = 0; nt < 4; nt++) {
            sc[nt][0] = __expf(sc[nt][0] - nm0); s0 += sc[nt][0];
            sc[nt][1] = __expf(sc[nt][1] - nm0); s0 += sc[nt][1];
            sc[nt][2] = __expf(sc[nt][2] - nm1); s1 += sc[nt][2];
            sc[nt][3] = __expf(sc[nt][3] - nm1); s1 += sc[nt][3];
        }
        l0 = l0*c0 + s0;
        l1 = l1*c1 + s1;

#pragma unroll
        for (int nt = 0; nt < 8; nt++) {
            o[nt][0] *= c0; o[nt][1] *= c0;
            o[nt][2] *= c1; o[nt][3] *= c1;
        }

        uint32_t src0 = (lane & ~3u) | ((uint32_t)tq >> 1);
        uint32_t src1 = src0 | 2u;
        bool odd = tq & 1;
#pragma unroll
        for (int c = 0; c < 4; c++) {
            float v00 = __shfl_sync(0xffffffffu, sc[c][0], src0);
            float v01 = __shfl_sync(0xffffffffu, sc[c][1], src0);
            float v10 = __shfl_sync(0xffffffffu, sc[c][2], src0);
            float v11 = __shfl_sync(0xffffffffu, sc[c][3], src0);
            float w00 = __shfl_sync(0xffffffffu, sc[c][0], src1);
            float w01 = __shfl_sync(0xffffffffu, sc[c][1], src1);
            float w10 = __shfl_sync(0xffffffffu, sc[c][2], src1);
            float w11 = __shfl_sync(0xffffffffu, sc[c][3], src1);
            uint32_t a[4];
            a[0] = f2tf32(odd ? v01 : v00);
            a[1] = f2tf32(odd ? v11 : v10);
            a[2] = f2tf32(odd ? w01 : w00);
            a[3] = f2tf32(odd ? w11 : w10);
#pragma unroll
            for (int nt = 0; nt < 8; nt++) {
                uint32_t bv[2];
                bv[0] = VsT[buf][c*8 + tq][nt*8 + gq];
                bv[1] = VsT[buf][c*8 + 4 + tq][nt*8 + gq];
                mma_tf32(o[nt], a, bv);
            }
        }

        if (more) {
            int nb = buf ^ 1;
#pragma unroll
            for (int it = 0; it < 4; it++) {
                int r = lr + it*8;
                KsI[nb][r][lj0*8 + 0 + lt0h] = f2tf32(kreg[it].x);
                KsI[nb][r][lj0*8 + 2 + lt0h] = f2tf32(kreg[it].y);
                KsI[nb][r][lj0*8 + 4 + lt0h] = f2tf32(kreg[it].z);
                KsI[nb][r][lj0*8 + 6 + lt0h] = f2tf32(kreg[it].w);
                uint4 vt;
                vt.x = f2tf32(vreg[it].x); vt.y = f2tf32(vreg[it].y);
                vt.z = f2tf32(vreg[it].z); vt.w = f2tf32(vreg[it].w);
                *(uint4*)&VsT[nb][r][lc] = vt;
            }
            if (tid < 32) Bias[nb][tid] = breg;
        }
        __syncthreads();
    }

    l0 += __shfl_xor_sync(0xffffffffu, l0, 1);
    l0 += __shfl_xor_sync(0xffffffffu, l0, 2);
    l1 += __shfl_xor_sync(0xffffffffu, l1, 1);
    l1 += __shfl_xor_sync(0xffffffffu, l1, 2);
    float inv0 = 1.0f / l0, inv1 = 1.0f / l1;
    __half* cb = ctx + ((size_t)(b*SS) + qb*64 + w*16) * HH + h*HD;
#pragma unroll
    for (int nt = 0; nt < 8; nt++) {
        __half2 u0 = __floats2half2_rn(o[nt][0]*inv0, o[nt][1]*inv0);
        __half2 u1 = __floats2half2_rn(o[nt][2]*inv1, o[nt][3]*inv1);
        *(__half2*)(cb + (size_t)gq*HH      + nt*8 + 2*tq) = u0;
        *(__half2*)(cb + (size_t)(gq+8)*HH  + nt*8 + 2*tq) = u1;
    }
}

// ---------------- launch ----------------
extern "C" void kernel_launch(void* const* d_in, const int* in_sizes, int n_in,
                              void* d_out, int out_size)
{
    const float* x     = (const float*)d_in[0];
    const int*   maskp = (const int*)  d_in[1];
    const float* nw    = (const float*)d_in[2];
    const float* nb    = (const float*)d_in[3];
    const float* qkvw  = (const float*)d_in[4];
    const float* qkvb  = (const float*)d_in[5];
    const float* ow    = (const float*)d_in[6];
    const float* ob    = (const float*)d_in[7];
    float* out = (float*)d_out;

    __half *xn, *ctx, *wq, *wo;
    float *qkvB;
    cudaGetSymbolAddress((void**)&xn,   g_xn);
    cudaGetSymbolAddress((void**)&qkvB, g_qkv);
    cudaGetSymbolAddress((void**)&ctx,  g_ctx);
    cudaGetSymbolAddress((void**)&wq,   g_wq);
    cudaGetSymbolAddress((void**)&wo,   g_wo);

    ln_kernel<<<BS, 256>>>(x, nw, nb, xn);
    transpose_w<<<dim3(H3/32, HH/32), dim3(32, 8)>>>(qkvw, wq, HH, H3);
    transpose_w<<<dim3(HH/32, HH/32), dim3(32, 8)>>>(ow,   wo, HH, HH);
    fp16_gemm<<<dim3(H3/128, BS/128), 128>>>(xn, wq, qkvb, qkvB, BS, H3, HH);
    rotary_kernel<<<(BS*NHH*32)/256, 256>>>(qkvB);
    attn_tc_kernel<<<dim3(SS/64, NHH, BB), 128>>>(qkvB, maskp, ctx);
    fp16_gemm<<<dim3(HH/128, BS/128), 128>>>(ctx, wo, ob, out, BS, HH, HH);
}